// round 8
// baseline (speedup 1.0000x reference)
#include <cuda_runtime.h>
#include <cstdint>

#define BATCH 20
#define SEQ   4096
#define EMB   256
#define NB    32
#define BLK   128
#define CTX   384
#define MROWS (BATCH*SEQ)

#define KC    16                        // k-chunk depth
#define SA16  20                        // A smem stride (floats), conflict-free frag reads
#define SBN   72                        // B smem stride (64 cols + 8 pad), conflict-free
#define ABUF  (128*SA16*4)              // 10240 B / stage
#define BBUF  (KC*SBN*4)                // 4608 B / stage
#define NSTG  4
#define SMEMB (NSTG*(ABUF+BBUF) + 512)  // 59904 B -> 3 CTAs/SM

// Scratch (device globals; no allocations allowed)
__device__ float g_xc[MROWS*EMB];
__device__ float g_wc[4*EMB*EMB];
__device__ float g_q [MROWS*EMB];
__device__ float g_kT[MROWS*EMB];                 // per block: [emb][token]
__device__ float g_v [MROWS*EMB];
__device__ float g_p [(size_t)BATCH*NB*BLK*CTX];  // exp(logits), valid windows only
__device__ float g_l [MROWS];                     // softmax row sums
__device__ float g_att[MROWS*EMB];

// ---- primitives -----------------------------------------------------------

__device__ __forceinline__ uint32_t smem_u32(const void* p) {
    uint32_t a;
    asm("{ .reg .u64 t; cvta.to.shared.u64 t, %1; cvt.u32.u64 %0, t; }"
        : "=r"(a) : "l"(p));
    return a;
}

__device__ __forceinline__ float totf(float x) {
    uint32_t r;
    asm("cvt.rna.tf32.f32 %0, %1;" : "=r"(r) : "f"(x));
    return __uint_as_float(r);
}

__device__ __forceinline__ void cpa16(uint32_t dst, const float* src) {
    asm volatile("cp.async.cg.shared.global [%0], [%1], 16;" :: "r"(dst), "l"(src));
}
#define CP_COMMIT() asm volatile("cp.async.commit_group;" ::: "memory")
#define CP_WAIT2()  asm volatile("cp.async.wait_group 2;" ::: "memory")

__device__ __forceinline__ void mma8(float c[4], float a0, float a1, float a2, float a3,
                                     float b0, float b1) {
    asm volatile(
        "mma.sync.aligned.m16n8k8.row.col.f32.tf32.tf32.f32 "
        "{%0,%1,%2,%3}, {%4,%5,%6,%7}, {%8,%9}, {%0,%1,%2,%3};"
        : "+f"(c[0]), "+f"(c[1]), "+f"(c[2]), "+f"(c[3])
        : "r"(__float_as_uint(a0)), "r"(__float_as_uint(a1)),
          "r"(__float_as_uint(a2)), "r"(__float_as_uint(a3)),
          "r"(__float_as_uint(b0)), "r"(__float_as_uint(b1)));
}

// ---- chunk copies (A: 128 x KC ; B: KC x 64) ------------------------------

__device__ __forceinline__ void cpA(uint32_t sA, const float* __restrict__ src,
                                    int ld, int t) {
#pragma unroll
    for (int j = 0; j < 2; j++) {
        int idx = j * 256 + t;
        int m = idx >> 2, k4 = (idx & 3) << 2;
        cpa16(sA + (uint32_t)(m * SA16 + k4) * 4, src + (size_t)m * ld + k4);
    }
}

__device__ __forceinline__ void cpB(uint32_t sB, const float* __restrict__ src,
                                    int ld, int t) {
    int k = t >> 4, n4 = (t & 15) << 2;
    cpa16(sB + (uint32_t)(k * SBN + n4) * 4, src + (size_t)k * ld + n4);
}

// ---- warp-tile compute: 32x32 per warp, one KC-deep chunk -----------------

__device__ __forceinline__ void mma_chunk(const float* __restrict__ As,
                                          const float* __restrict__ Bs,
                                          float acc[8][4], int t) {
    int lane = t & 31, w = t >> 5;
    int g = lane >> 2, tig = lane & 3;
    int mbase = (w >> 1) * 32 + g;
    int nbase = (w & 1) * 32 + g;
#pragma unroll
    for (int s = 0; s < 2; s++) {
        int k = s * 8 + tig;
        float b[4][2];
#pragma unroll
        for (int nt = 0; nt < 4; nt++) {
            b[nt][0] = Bs[k * SBN + nbase + nt * 8];
            b[nt][1] = Bs[(k + 4) * SBN + nbase + nt * 8];
        }
#pragma unroll
        for (int mt = 0; mt < 2; mt++) {
            int m = mbase + mt * 16;
            float a0 = As[m * SA16 + k];
            float a1 = As[(m + 8) * SA16 + k];
            float a2 = As[m * SA16 + k + 4];
            float a3 = As[(m + 8) * SA16 + k + 4];
#pragma unroll
            for (int nt = 0; nt < 4; nt++)
                mma8(acc[mt * 4 + nt], a0, a1, a2, a3, b[nt][0], b[nt][1]);
        }
    }
}

// ---- 4-stage pipeline, one __syncthreads per chunk ------------------------
// chunk c: A at Abase + c*aStep, B at Bbase + c*bStep (affine)

__device__ __forceinline__ void gemm_pipeline(const float* __restrict__ Abase, int aStep, int lda,
                                              const float* __restrict__ Bbase, int bStep, int ldb,
                                              int nC, float acc[8][4], char* smem, int t) {
    uint32_t aA[NSTG], bA[NSTG];
    const float* Ap[NSTG];
    const float* Bp[NSTG];
#pragma unroll
    for (int i = 0; i < NSTG; i++) {
        Ap[i] = (const float*)(smem + i * ABUF);
        Bp[i] = (const float*)(smem + NSTG * ABUF + i * BBUF);
        aA[i] = smem_u32(Ap[i]);
        bA[i] = smem_u32(Bp[i]);
    }
#pragma unroll
    for (int i = 0; i < 3; i++) {          // nC >= 16 always
        cpA(aA[i], Abase + (size_t)i * aStep, lda, t);
        cpB(bA[i], Bbase + (size_t)i * bStep, ldb, t);
        CP_COMMIT();
    }

    int bufc = 0, bufn = 3;
    for (int c = 0; c < nC; c++) {
        CP_WAIT2();                         // chunk c landed (3 groups pending -> <=2)
        __syncthreads();
        if (c + 3 < nC) {
            cpA(aA[bufn], Abase + (size_t)(c + 3) * aStep, lda, t);
            cpB(bA[bufn], Bbase + (size_t)(c + 3) * bStep, ldb, t);
        }
        CP_COMMIT();                        // empty group at tail keeps count correct
        mma_chunk(Ap[bufc], Bp[bufc], acc, t);
        bufc = (bufc + 1) & 3;
        bufn = (bufn + 1) & 3;
    }
}

// ---- standard epilogue ----------------------------------------------------

__device__ __forceinline__ void store_std(float acc[8][4], float* __restrict__ C, int ldc,
                                          const float* __restrict__ bias,
                                          bool rnd, int t) {
    int lane = t & 31, w = t >> 5;
    int g = lane >> 2, tig = lane & 3;
    int mbase = (w >> 1) * 32 + g;
    int nbase = (w & 1) * 32 + 2 * tig;
#pragma unroll
    for (int mt = 0; mt < 2; mt++) {
#pragma unroll
        for (int nt = 0; nt < 4; nt++) {
            float* c4 = acc[mt * 4 + nt];
            int m = mbase + mt * 16, n = nbase + nt * 8;
            float v0 = c4[0], v1 = c4[1], v2 = c4[2], v3 = c4[3];
            if (bias) { v0 += bias[n]; v1 += bias[n + 1]; v2 += bias[n]; v3 += bias[n + 1]; }
            if (rnd) { v0 = totf(v0); v1 = totf(v1); v2 = totf(v2); v3 = totf(v3); }
            *(float2*)(C + (size_t)m * ldc + n)       = make_float2(v0, v1);
            *(float2*)(C + (size_t)(m + 8) * ldc + n) = make_float2(v2, v3);
        }
    }
}

// ---- kernel 0: tf32-round x and all four weights (one launch) -------------

#define XF4 (MROWS*EMB/4)
__global__ __launch_bounds__(256)
void cvt_kernel(const float* __restrict__ x,
                const float* __restrict__ Wq, const float* __restrict__ Wk,
                const float* __restrict__ Wv, const float* __restrict__ Wo) {
    int i = blockIdx.x * 256 + threadIdx.x;
    const float* src;
    float* dst;
    if (i < XF4) {
        src = x; dst = g_xc;
    } else {
        int r = i - XF4;
        int wsel = r >> 14;
        src = (wsel == 0) ? Wq : (wsel == 1) ? Wk : (wsel == 2) ? Wv : Wo;
        dst = g_wc + ((size_t)(r & ~16383) << 2);
        i = r & 16383;
        // note: dst indexed by (r&16383) below via i
        float4 v = ((const float4*)src)[i];
        v.x = totf(v.x); v.y = totf(v.y); v.z = totf(v.z); v.w = totf(v.w);
        ((float4*)dst)[i] = v;
        return;
    }
    float4 v = ((const float4*)src)[i];
    v.x = totf(v.x); v.y = totf(v.y); v.z = totf(v.z); v.w = totf(v.w);
    ((float4*)dst)[i] = v;
}

// init row sums with padded-context contribution: 128 * exp(0) per missing block
__global__ __launch_bounds__(256)
void linit_kernel() {
    int i = blockIdx.x * 256 + threadIdx.x;
    int nbi = (i >> 7) & (NB - 1);
    g_l[i] = 128.0f * (float)((nbi == 0) + (nbi == NB - 1));
}

// ---- kernel 1: QKV projections. grid (12 = z*4+ntile, 640 m) --------------

__global__ __launch_bounds__(256, 3)
void qkv_mma() {
    extern __shared__ char smbuf[];
    int t = threadIdx.x;
    int z = blockIdx.x >> 2, ntile = blockIdx.x & 3;
    int m0 = blockIdx.y * 128, n0 = ntile * 64;

    float acc[8][4] = {};
    gemm_pipeline(g_xc + (size_t)m0 * EMB, KC, EMB,
                  g_wc + (size_t)z * EMB * EMB + n0, KC * EMB, EMB,
                  EMB / KC, acc, smbuf, t);

    if (z == 1) {
        // transposed store into g_kT: [block][emb][token]
        float* KT = g_kT + (size_t)m0 * EMB + (size_t)n0 * 128;
        int lane = t & 31, w = t >> 5;
        int g = lane >> 2, tig = lane & 3;
        int mbase = (w >> 1) * 32 + g;
        int nbase = (w & 1) * 32 + 2 * tig;
#pragma unroll
        for (int mt = 0; mt < 2; mt++) {
#pragma unroll
            for (int nt = 0; nt < 4; nt++) {
                float* c4 = acc[mt * 4 + nt];
                int m = mbase + mt * 16, n = nbase + nt * 8;
                KT[(size_t)n * 128 + m]           = totf(c4[0]);
                KT[(size_t)(n + 1) * 128 + m]     = totf(c4[1]);
                KT[(size_t)n * 128 + m + 8]       = totf(c4[2]);
                KT[(size_t)(n + 1) * 128 + m + 8] = totf(c4[3]);
            }
        }
    } else {
        float* C = (z == 0 ? g_q : g_v) + (size_t)m0 * EMB + n0;
        store_std(acc, C, EMB, nullptr, true, t);
    }
}

// ---- kernel 2: P = exp(Q@K^T/16), row sums. grid (6 = cj*2+ntile, NB, B) --

__global__ __launch_bounds__(256, 3)
void qk_mma() {
    extern __shared__ char smbuf[];
    float* ls = (float*)(smbuf + NSTG * (ABUF + BBUF));
    int t = threadIdx.x;
    int cj = blockIdx.x >> 1, ntile = blockIdx.x & 1;
    int nbi = blockIdx.y, b = blockIdx.z;
    int gb = nbi + cj - 1;
    if (gb < 0 || gb >= NB) return;             // padded: handled by linit

    if (t < 128) ls[t] = 0.f;                   // ordered by pipeline's first barrier
    int n0 = ntile * 64;                        // token sub-tile

    float acc[8][4] = {};
    gemm_pipeline(g_q + (size_t)(b * SEQ + nbi * BLK) * EMB, KC, EMB,
                  g_kT + (size_t)(b * SEQ + gb * BLK) * EMB + n0, KC * 128, 128,
                  EMB / KC, acc, smbuf, t);

    float* P = g_p + ((size_t)(b * NB + nbi) * BLK) * CTX + cj * BLK + n0;
    int lane = t & 31, w = t >> 5;
    int g = lane >> 2, tig = lane & 3;
    int mbase = (w >> 1) * 32 + g;
    int nbase = (w & 1) * 32 + 2 * tig;
    float rsum[4] = {0.f, 0.f, 0.f, 0.f};
#pragma unroll
    for (int mt = 0; mt < 2; mt++) {
#pragma unroll
        for (int nt = 0; nt < 4; nt++) {
            float* c4 = acc[mt * 4 + nt];
            int m = mbase + mt * 16, n = nbase + nt * 8;
            float e0 = __expf(c4[0] * 0.0625f);
            float e1 = __expf(c4[1] * 0.0625f);
            float e2 = __expf(c4[2] * 0.0625f);
            float e3 = __expf(c4[3] * 0.0625f);
            rsum[mt * 2 + 0] += e0 + e1;
            rsum[mt * 2 + 1] += e2 + e3;
            *(float2*)(P + (size_t)m * CTX + n)       = make_float2(totf(e0), totf(e1));
            *(float2*)(P + (size_t)(m + 8) * CTX + n) = make_float2(totf(e2), totf(e3));
        }
    }
#pragma unroll
    for (int i = 0; i < 4; i++) {
        rsum[i] += __shfl_xor_sync(0xFFFFFFFFu, rsum[i], 1);
        rsum[i] += __shfl_xor_sync(0xFFFFFFFFu, rsum[i], 2);
    }
    if (tig == 0) {
#pragma unroll
        for (int i = 0; i < 4; i++)
            atomicAdd(&ls[mbase + (i >> 1) * 16 + (i & 1) * 8], rsum[i]);
    }
    __syncthreads();
    if (t < 128)
        atomicAdd(&g_l[(size_t)(b * NB + nbi) * 128 + t], ls[t]);
}

// ---- kernel 3: O = (P @ Vc) / l, permuted store. grid (4 ntile, NB, B) ----

__global__ __launch_bounds__(256, 3)
void av_mma() {
    extern __shared__ char smbuf[];
    int t = threadIdx.x;
    int n0 = blockIdx.x * 64;
    int nbi = blockIdx.y, b = blockIdx.z;

    int lo = (nbi == 0) ? 1 : 0;
    int hi = (nbi == NB - 1) ? 1 : 2;
    int nC = (hi - lo + 1) * (BLK / KC);
    int gb0 = nbi + lo - 1;

    float acc[8][4] = {};
    gemm_pipeline(g_p + (size_t)((b * NB + nbi) * BLK) * CTX + lo * BLK, KC, CTX,
                  g_v + (size_t)(b * SEQ + gb0 * BLK) * EMB + n0, KC * EMB, EMB,
                  nC, acc, smbuf, t);

    const float* lrow = g_l + (size_t)(b * NB + nbi) * 128;
    int rowbase = nbi * (BATCH * BLK) + b * BLK;   // reference transpose (1,0,2,3)
    float* C = g_att + (size_t)rowbase * EMB + n0;

    int lane = t & 31, w = t >> 5;
    int g = lane >> 2, tig = lane & 3;
    int mbase = (w >> 1) * 32 + g;
    int nbase = (w & 1) * 32 + 2 * tig;
#pragma unroll
    for (int mt = 0; mt < 2; mt++) {
        int m = mbase + mt * 16;
        float inv0 = 1.0f / lrow[m];
        float inv1 = 1.0f / lrow[m + 8];
#pragma unroll
        for (int nt = 0; nt < 4; nt++) {
            float* c4 = acc[mt * 4 + nt];
            int n = nbase + nt * 8;
            *(float2*)(C + (size_t)m * EMB + n) =
                make_float2(totf(c4[0] * inv0), totf(c4[1] * inv0));
            *(float2*)(C + (size_t)(m + 8) * EMB + n) =
                make_float2(totf(c4[2] * inv1), totf(c4[3] * inv1));
        }
    }
}

// ---- kernel 4: out = att @ Wo + bo. grid (4 ntile, 640 m) -----------------

__global__ __launch_bounds__(256, 3)
void out_mma(const float* __restrict__ bo, float* __restrict__ out) {
    extern __shared__ char smbuf[];
    int t = threadIdx.x;
    int n0 = blockIdx.x * 64, m0 = blockIdx.y * 128;

    float acc[8][4] = {};
    gemm_pipeline(g_att + (size_t)m0 * EMB, KC, EMB,
                  g_wc + (size_t)3 * EMB * EMB + n0, KC * EMB, EMB,
                  EMB / KC, acc, smbuf, t);
    store_std(acc, out + (size_t)m0 * EMB + n0, EMB, bo + n0, false, t);
}

// ---- launch ---------------------------------------------------------------

extern "C" void kernel_launch(void* const* d_in, const int* in_sizes, int n_in,
                              void* d_out, int out_size) {
    const float* x  = (const float*)d_in[0];
    const float* Wq = (const float*)d_in[1];
    const float* Wk = (const float*)d_in[2];
    const float* Wv = (const float*)d_in[3];
    const float* Wo = (const float*)d_in[4];
    const float* bo = (const float*)d_in[5];
    float* out = (float*)d_out;

    cudaFuncSetAttribute(qkv_mma, cudaFuncAttributeMaxDynamicSharedMemorySize, SMEMB);
    cudaFuncSetAttribute(qk_mma,  cudaFuncAttributeMaxDynamicSharedMemorySize, SMEMB);
    cudaFuncSetAttribute(av_mma,  cudaFuncAttributeMaxDynamicSharedMemorySize, SMEMB);
    cudaFuncSetAttribute(out_mma, cudaFuncAttributeMaxDynamicSharedMemorySize, SMEMB);

    cvt_kernel<<<(XF4 + 4 * 16384 + 255) / 256, 256>>>(x, Wq, Wk, Wv, Wo);
    linit_kernel<<<MROWS / 256, 256>>>();

    qkv_mma<<<dim3(12, MROWS / 128), 256, SMEMB>>>();
    qk_mma<<<dim3(6, NB, BATCH), 256, SMEMB>>>();
    av_mma<<<dim3(4, NB, BATCH), 256, SMEMB>>>();
    out_mma<<<dim3(4, MROWS / 128), 256, SMEMB>>>(bo, out);
}

// round 10
// speedup vs baseline: 1.3102x; 1.3102x over previous
#include <cuda_runtime.h>
#include <cuda_fp16.h>
#include <cstdint>

#define BATCH 20
#define SEQ   4096
#define EMB   256
#define NB    32
#define BLK   128
#define CTX   384
#define MROWS (BATCH*SEQ)

#define SA   36                          // fp32 A smem stride (b32), conflict-free
#define SB   136                         // fp32 B smem stride (b32), conflict-free
#define ABUF (128*SA*4)                  // 18432 B
#define BBUF (32*SB*4)                   // 17408 B
#define SMEMB    (3*ABUF + 3*BBUF + 512) // 108032 B  (qk / out)
#define SMEM_QKV (2*ABUF + 3*BBUF)       // 89088 B   (qkv: A double-buf + B 3-stage)

#define SAH  20                          // fp16 tile stride in b32 units (16 words + 4 pad)
#define ABH  (128*SAH*4)                 // 10240 B per fp16 stage
#define SMEM_AV (6*ABH + 256)            // 61696 B   (av: 3 A + 3 B stages)

// Scratch (device globals; no allocations allowed)
__device__ float  g_wc[4*EMB*EMB];
__device__ float  g_q [MROWS*EMB];
__device__ float  g_kT[MROWS*EMB];                  // per 128-row block: [emb][token]
__device__ __half g_vT[MROWS*EMB];                  // per 128-row block: [emb][token], fp16
__device__ __half g_p [(size_t)BATCH*NB*BLK*CTX];   // exp(logits), fp16
__device__ float  g_l [MROWS];                      // softmax row sums
__device__ float  g_att[MROWS*EMB];

// ---- primitives -----------------------------------------------------------

__device__ __forceinline__ uint32_t smem_u32(const void* p) {
    uint32_t a;
    asm("{ .reg .u64 t; cvta.to.shared.u64 t, %1; cvt.u32.u64 %0, t; }"
        : "=r"(a) : "l"(p));
    return a;
}

__device__ __forceinline__ float totf(float x) {
    uint32_t r;
    asm("cvt.rna.tf32.f32 %0, %1;" : "=r"(r) : "f"(x));
    return __uint_as_float(r);
}

__device__ __forceinline__ void cpa16(uint32_t dst, const void* src) {
    asm volatile("cp.async.cg.shared.global [%0], [%1], 16;" :: "r"(dst), "l"(src));
}
#define CP_COMMIT() asm volatile("cp.async.commit_group;" ::: "memory")
#define CP_WAIT1()  asm volatile("cp.async.wait_group 1;" ::: "memory")
#define CP_WAIT0()  asm volatile("cp.async.wait_group 0;" ::: "memory")

__device__ __forceinline__ void mma8(float c[4], float a0, float a1, float a2, float a3,
                                     float b0, float b1) {
    asm volatile(
        "mma.sync.aligned.m16n8k8.row.col.f32.tf32.tf32.f32 "
        "{%0,%1,%2,%3}, {%4,%5,%6,%7}, {%8,%9}, {%0,%1,%2,%3};"
        : "+f"(c[0]), "+f"(c[1]), "+f"(c[2]), "+f"(c[3])
        : "r"(__float_as_uint(a0)), "r"(__float_as_uint(a1)),
          "r"(__float_as_uint(a2)), "r"(__float_as_uint(a3)),
          "r"(__float_as_uint(b0)), "r"(__float_as_uint(b1)));
}

__device__ __forceinline__ void mma16h(float c[4], uint32_t a0, uint32_t a1,
                                       uint32_t a2, uint32_t a3,
                                       uint32_t b0, uint32_t b1) {
    asm volatile(
        "mma.sync.aligned.m16n8k16.row.col.f32.f16.f16.f32 "
        "{%0,%1,%2,%3}, {%4,%5,%6,%7}, {%8,%9}, {%0,%1,%2,%3};"
        : "+f"(c[0]), "+f"(c[1]), "+f"(c[2]), "+f"(c[3])
        : "r"(a0), "r"(a1), "r"(a2), "r"(a3), "r"(b0), "r"(b1));
}

// ---- fp32 chunk copies (A: 128x32 ; B: 32x128) ----------------------------

__device__ __forceinline__ void cpA(uint32_t sA, const float* __restrict__ src,
                                    int ld, int t) {
#pragma unroll
    for (int j = 0; j < 4; j++) {
        int idx = j * 256 + t;
        int m = idx >> 3, k4 = (idx & 7) << 2;
        cpa16(sA + (uint32_t)(m * SA + k4) * 4, src + (size_t)m * ld + k4);
    }
}

__device__ __forceinline__ void cpB(uint32_t sB, const float* __restrict__ src,
                                    int ld, int t) {
#pragma unroll
    for (int j = 0; j < 4; j++) {
        int idx = j * 256 + t;
        int k = idx >> 5, n4 = (idx & 31) << 2;
        cpa16(sB + (uint32_t)(k * SB + n4) * 4, src + (size_t)k * ld + n4);
    }
}

// ---- fp32 warp-tile (64x32) compute for one 32-deep chunk -----------------

__device__ __forceinline__ void mma_chunk(const float* __restrict__ As,
                                          const float* __restrict__ Bs,
                                          float acc[16][4], int t) {
    int lane = t & 31, w = t >> 5;
    int g = lane >> 2, tig = lane & 3;
    int mbase = (w >> 2) * 64 + g;
    int nbase = (w & 3) * 32 + g;
#pragma unroll
    for (int s = 0; s < 4; s++) {
        int k = s * 8 + tig;
        float b[4][2];
#pragma unroll
        for (int nt = 0; nt < 4; nt++) {
            b[nt][0] = Bs[k * SB + nbase + nt * 8];
            b[nt][1] = Bs[(k + 4) * SB + nbase + nt * 8];
        }
#pragma unroll
        for (int mt = 0; mt < 4; mt++) {
            int m = mbase + mt * 16;
            float a0 = As[m * SA + k];
            float a1 = As[(m + 8) * SA + k];
            float a2 = As[m * SA + k + 4];
            float a3 = As[(m + 8) * SA + k + 4];
#pragma unroll
            for (int nt = 0; nt < 4; nt++)
                mma8(acc[mt * 4 + nt], a0, a1, a2, a3, b[nt][0], b[nt][1]);
        }
    }
}

// ---- fp32 3-stage pipeline (qk, out) --------------------------------------

__device__ __forceinline__ void gemm_pipeline(const float* __restrict__ Abase, int aStep, int lda,
                                              const float* __restrict__ Bbase, int bStep, int ldb,
                                              int nC, float acc[16][4], char* smem, int t) {
    uint32_t aA[3], bA[3];
    const float* Ap[3];
    const float* Bp[3];
#pragma unroll
    for (int i = 0; i < 3; i++) {
        Ap[i] = (const float*)(smem + i * ABUF);
        Bp[i] = (const float*)(smem + 3 * ABUF + i * BBUF);
        aA[i] = smem_u32(Ap[i]);
        bA[i] = smem_u32(Bp[i]);
    }
    cpA(aA[0], Abase, lda, t);
    cpB(bA[0], Bbase, ldb, t);
    CP_COMMIT();
    cpA(aA[1], Abase + aStep, lda, t);
    cpB(bA[1], Bbase + (size_t)bStep, ldb, t);
    CP_COMMIT();

    int bufc = 0, bufn = 2;
    for (int c = 0; c < nC; c++) {
        if (c < nC - 1) CP_WAIT1(); else CP_WAIT0();
        __syncthreads();
        if (c + 2 < nC) {
            cpA(aA[bufn], Abase + (size_t)(c + 2) * aStep, lda, t);
            cpB(bA[bufn], Bbase + (size_t)(c + 2) * bStep, ldb, t);
            CP_COMMIT();
        }
        mma_chunk(Ap[bufc], Bp[bufc], acc, t);
        bufc = (bufc == 2) ? 0 : bufc + 1;
        bufn = (bufn == 2) ? 0 : bufn + 1;
    }
}

// ---- standard fp32 epilogue -----------------------------------------------

__device__ __forceinline__ void store_std(float acc[16][4], float* __restrict__ C, int ldc,
                                          const float* __restrict__ bias,
                                          bool rnd, int t) {
    int lane = t & 31, w = t >> 5;
    int g = lane >> 2, tig = lane & 3;
    int mbase = (w >> 2) * 64 + g;
    int nbase = (w & 3) * 32 + 2 * tig;
#pragma unroll
    for (int mt = 0; mt < 4; mt++) {
#pragma unroll
        for (int nt = 0; nt < 4; nt++) {
            float* c4 = acc[mt * 4 + nt];
            int m = mbase + mt * 16, n = nbase + nt * 8;
            float v0 = c4[0], v1 = c4[1], v2 = c4[2], v3 = c4[3];
            if (bias) { v0 += bias[n]; v1 += bias[n + 1]; v2 += bias[n]; v3 += bias[n + 1]; }
            if (rnd) { v0 = totf(v0); v1 = totf(v1); v2 = totf(v2); v3 = totf(v3); }
            *(float2*)(C + (size_t)m * ldc + n)       = make_float2(v0, v1);
            *(float2*)(C + (size_t)(m + 8) * ldc + n) = make_float2(v2, v3);
        }
    }
}

// ---- helper kernels -------------------------------------------------------

__global__ __launch_bounds__(256)
void wcvt_kernel(const float* __restrict__ Wq, const float* __restrict__ Wk,
                 const float* __restrict__ Wv, const float* __restrict__ Wo) {
    int i = blockIdx.x * 256 + threadIdx.x;       // 4*16384 float4s
    int wsel = i >> 14, r = i & 16383;
    const float* src = (wsel == 0) ? Wq : (wsel == 1) ? Wk : (wsel == 2) ? Wv : Wo;
    float4 v = ((const float4*)src)[r];
    v.x = totf(v.x); v.y = totf(v.y); v.z = totf(v.z); v.w = totf(v.w);
    ((float4*)g_wc)[i] = v;
}

__global__ __launch_bounds__(256)
void linit_kernel() {
    int i = blockIdx.x * 256 + threadIdx.x;
    int nbi = (i >> 7) & (NB - 1);
    g_l[i] = 128.0f * (float)((nbi == 0) + (nbi == NB - 1));  // exp(0) padded keys
}

// ---- kernel 1: QKV. A from raw x via LDG+cvt+STS; grid (6=z*2+nt, 640) ----

__device__ __forceinline__ void ldgA(float4 ar[4], const float* __restrict__ src, int t) {
#pragma unroll
    for (int j = 0; j < 4; j++) {
        int idx = j * 256 + t;
        int m = idx >> 3, k4 = (idx & 7) << 2;
        ar[j] = *(const float4*)(src + (size_t)m * EMB + k4);
    }
}

__device__ __forceinline__ void stsA(float* __restrict__ As, const float4 ar[4], int t) {
#pragma unroll
    for (int j = 0; j < 4; j++) {
        int idx = j * 256 + t;
        int m = idx >> 3, k4 = (idx & 7) << 2;
        float4 v = ar[j];
        v.x = totf(v.x); v.y = totf(v.y); v.z = totf(v.z); v.w = totf(v.w);
        *(float4*)(As + m * SA + k4) = v;
    }
}

__global__ __launch_bounds__(256, 2)
void qkv_mma(const float* __restrict__ x) {
    extern __shared__ char smbuf[];
    int t = threadIdx.x;
    int z = blockIdx.x >> 1, ntile = blockIdx.x & 1;
    int m0 = blockIdx.y * 128, n0 = ntile * 128;
    const float* Ax = x + (size_t)m0 * EMB;
    const float* Bw = g_wc + (size_t)z * EMB * EMB + n0;

    float* Ab[2] = {(float*)smbuf, (float*)(smbuf + ABUF)};
    uint32_t bA[3];
    const float* Bp[3];
#pragma unroll
    for (int i = 0; i < 3; i++) {
        Bp[i] = (const float*)(smbuf + 2 * ABUF + i * BBUF);
        bA[i] = smem_u32(Bp[i]);
    }

    float4 ar[4];
    ldgA(ar, Ax, t);
    cpB(bA[0], Bw, EMB, t);
    CP_COMMIT();
    cpB(bA[1], Bw + (size_t)32 * EMB, EMB, t);
    CP_COMMIT();

    float acc[16][4] = {};
    for (int c = 0; c < 8; c++) {
        stsA(Ab[c & 1], ar, t);
        if (c < 7) CP_WAIT1(); else CP_WAIT0();
        __syncthreads();
        if (c + 2 < 8) {
            cpB(bA[(c + 2) % 3], Bw + (size_t)(c + 2) * 32 * EMB, EMB, t);
            CP_COMMIT();
        }
        if (c + 1 < 8) ldgA(ar, Ax + (c + 1) * 32, t);
        mma_chunk(Ab[c & 1], Bp[c % 3], acc, t);
    }

    int lane = t & 31, w = t >> 5;
    int g = lane >> 2, tig = lane & 3;
    int mbase = (w >> 2) * 64 + g;
    int nbase = (w & 3) * 32 + 2 * tig;

    if (z == 0) {
        store_std(acc, g_q + (size_t)m0 * EMB + n0, EMB, nullptr, true, t);
    } else if (z == 1) {
        float* KT = g_kT + (size_t)m0 * EMB + (size_t)n0 * 128;  // [emb][token]
#pragma unroll
        for (int mt = 0; mt < 4; mt++) {
#pragma unroll
            for (int nt = 0; nt < 4; nt++) {
                float* c4 = acc[mt * 4 + nt];
                int m = mbase + mt * 16, n = nbase + nt * 8;
                KT[(size_t)n * 128 + m]           = totf(c4[0]);
                KT[(size_t)(n + 1) * 128 + m]     = totf(c4[1]);
                KT[(size_t)n * 128 + m + 8]       = totf(c4[2]);
                KT[(size_t)(n + 1) * 128 + m + 8] = totf(c4[3]);
            }
        }
    } else {
        __half* VT = g_vT + (size_t)m0 * EMB + (size_t)n0 * 128;  // [emb][token] fp16
#pragma unroll
        for (int mt = 0; mt < 4; mt++) {
#pragma unroll
            for (int nt = 0; nt < 4; nt++) {
                float* c4 = acc[mt * 4 + nt];
                int m = mbase + mt * 16, n = nbase + nt * 8;
                VT[(size_t)n * 128 + m]           = __float2half_rn(c4[0]);
                VT[(size_t)(n + 1) * 128 + m]     = __float2half_rn(c4[1]);
                VT[(size_t)n * 128 + m + 8]       = __float2half_rn(c4[2]);
                VT[(size_t)(n + 1) * 128 + m + 8] = __float2half_rn(c4[3]);
            }
        }
    }
}

// ---- kernel 2: P = exp(Q@K^T/16) (fp16 store), row sums. grid (3,NB,B) ----

__global__ __launch_bounds__(256, 2)
void qk_mma() {
    extern __shared__ char smbuf[];
    float* ls = (float*)(smbuf + 3 * ABUF + 3 * BBUF);
    int t = threadIdx.x;
    int cj = blockIdx.x, nbi = blockIdx.y, b = blockIdx.z;
    int gb = nbi + cj - 1;
    if (gb < 0 || gb >= NB) return;             // padded: handled by linit

    if (t < 128) ls[t] = 0.f;                   // ordered by pipeline's first barrier

    float acc[16][4] = {};
    gemm_pipeline(g_q + (size_t)(b * SEQ + nbi * BLK) * EMB, 32, EMB,
                  g_kT + (size_t)(b * SEQ + gb * BLK) * EMB, 32 * 128, 128,
                  8, acc, smbuf, t);

    __half* P = g_p + ((size_t)(b * NB + nbi) * BLK) * CTX + cj * BLK;
    int lane = t & 31, w = t >> 5;
    int g = lane >> 2, tig = lane & 3;
    int mbase = (w >> 2) * 64 + g;
    int nbase = (w & 3) * 32 + 2 * tig;
    float rsum[8];
#pragma unroll
    for (int i = 0; i < 8; i++) rsum[i] = 0.f;
#pragma unroll
    for (int mt = 0; mt < 4; mt++) {
#pragma unroll
        for (int nt = 0; nt < 4; nt++) {
            float* c4 = acc[mt * 4 + nt];
            int m = mbase + mt * 16, n = nbase + nt * 8;
            float e0 = __expf(c4[0] * 0.0625f);
            float e1 = __expf(c4[1] * 0.0625f);
            float e2 = __expf(c4[2] * 0.0625f);
            float e3 = __expf(c4[3] * 0.0625f);
            rsum[mt * 2 + 0] += e0 + e1;
            rsum[mt * 2 + 1] += e2 + e3;
            *(__half2*)(P + (size_t)m * CTX + n)       = __floats2half2_rn(e0, e1);
            *(__half2*)(P + (size_t)(m + 8) * CTX + n) = __floats2half2_rn(e2, e3);
        }
    }
#pragma unroll
    for (int i = 0; i < 8; i++) {
        rsum[i] += __shfl_xor_sync(0xFFFFFFFFu, rsum[i], 1);
        rsum[i] += __shfl_xor_sync(0xFFFFFFFFu, rsum[i], 2);
    }
    if (tig == 0) {
#pragma unroll
        for (int i = 0; i < 8; i++)
            atomicAdd(&ls[mbase + (i >> 1) * 16 + (i & 1) * 8], rsum[i]);
    }
    __syncthreads();
    if (t < 128)
        atomicAdd(&g_l[(size_t)(b * NB + nbi) * 128 + t], ls[t]);
}

// ---- kernel 3: O = (P @ Vc)/l in fp16 MMA. grid (2 ntile, NB, B) ----------

// FIXED: full-tile copy — 128 rows x 32 halves = 8192 B = 512 x 16 B (2 per thread)
__device__ __forceinline__ void cpH(uint32_t sD, const __half* __restrict__ src,
                                    int ldh, int t) {
#pragma unroll
    for (int j = 0; j < 2; j++) {
        int idx = j * 256 + t;
        int r = idx >> 2, seg = idx & 3;
        cpa16(sD + (uint32_t)(r * SAH + seg * 4) * 4, src + (size_t)r * ldh + seg * 8);
    }
}

__device__ __forceinline__ void mma_chunk_h(const uint32_t* __restrict__ As,
                                            const uint32_t* __restrict__ Bs,
                                            float acc[16][4], int t) {
    int lane = t & 31, w = t >> 5;
    int g = lane >> 2, tig = lane & 3;
    int mbase = (w >> 2) * 64 + g;
    int nbase = (w & 3) * 32 + g;
#pragma unroll
    for (int s = 0; s < 2; s++) {
        int ko = s * 8 + tig;
        uint32_t b[4][2];
#pragma unroll
        for (int nt = 0; nt < 4; nt++) {
            b[nt][0] = Bs[(nbase + nt * 8) * SAH + ko];
            b[nt][1] = Bs[(nbase + nt * 8) * SAH + ko + 4];
        }
#pragma unroll
        for (int mt = 0; mt < 4; mt++) {
            int m = mbase + mt * 16;
            uint32_t a0 = As[m * SAH + ko];
            uint32_t a1 = As[(m + 8) * SAH + ko];
            uint32_t a2 = As[m * SAH + ko + 4];
            uint32_t a3 = As[(m + 8) * SAH + ko + 4];
#pragma unroll
            for (int nt = 0; nt < 4; nt++)
                mma16h(acc[mt * 4 + nt], a0, a1, a2, a3, b[nt][0], b[nt][1]);
        }
    }
}

__global__ __launch_bounds__(256, 2)
void av_mma() {
    extern __shared__ char smbuf[];
    int t = threadIdx.x;
    int n0 = blockIdx.x * 128;
    int nbi = blockIdx.y, b = blockIdx.z;

    int lo = (nbi == 0) ? 1 : 0;
    int hi = (nbi == NB - 1) ? 1 : 2;
    int nC = (hi - lo + 1) * 4;                  // 32-token chunks
    int gb0 = nbi + lo - 1;

    const __half* Pb = g_p + (size_t)((b * NB + nbi) * BLK) * CTX + lo * BLK;
    // vT chunk base for chunk c: block gb0 + (c>>2), tokens (c&3)*32
    const __half* Vt0 = g_vT + (size_t)(b * SEQ + gb0 * BLK) * EMB + (size_t)n0 * 128;

    uint32_t aA[3], bA[3];
    const uint32_t* Ap[3];
    const uint32_t* Bp[3];
#pragma unroll
    for (int i = 0; i < 3; i++) {
        Ap[i] = (const uint32_t*)(smbuf + i * ABH);
        Bp[i] = (const uint32_t*)(smbuf + 3 * ABH + i * ABH);
        aA[i] = smem_u32(Ap[i]);
        bA[i] = smem_u32(Bp[i]);
    }
#pragma unroll
    for (int i = 0; i < 2; i++) {
        cpH(aA[i], Pb + i * 32, CTX, t);
        cpH(bA[i], Vt0 + ((size_t)(i >> 2) * BLK * EMB) + (i & 3) * 32, 128, t);
        CP_COMMIT();
    }

    float acc[16][4] = {};
    int bufc = 0, bufn = 2;
    for (int c = 0; c < nC; c++) {
        if (c < nC - 1) CP_WAIT1(); else CP_WAIT0();
        __syncthreads();
        if (c + 2 < nC) {
            int cn = c + 2;
            cpH(aA[bufn], Pb + cn * 32, CTX, t);
            cpH(bA[bufn], Vt0 + ((size_t)(cn >> 2) * BLK * EMB) + (cn & 3) * 32, 128, t);
            CP_COMMIT();
        }
        mma_chunk_h(Ap[bufc], Bp[bufc], acc, t);
        bufc = (bufc == 2) ? 0 : bufc + 1;
        bufn = (bufn == 2) ? 0 : bufn + 1;
    }

    const float* lrow = g_l + (size_t)(b * NB + nbi) * 128;
    int rowbase = nbi * (BATCH * BLK) + b * BLK;   // reference transpose (1,0,2,3)
    float* C = g_att + (size_t)rowbase * EMB + n0;

    int lane = t & 31, w = t >> 5;
    int g = lane >> 2, tig = lane & 3;
    int mbase = (w >> 2) * 64 + g;
    int nbase = (w & 3) * 32 + 2 * tig;
#pragma unroll
    for (int mt = 0; mt < 4; mt++) {
        int m = mbase + mt * 16;
        float inv0 = 1.0f / lrow[m];
        float inv1 = 1.0f / lrow[m + 8];
#pragma unroll
        for (int nt = 0; nt < 4; nt++) {
            float* c4 = acc[mt * 4 + nt];
            int n = nbase + nt * 8;
            *(float2*)(C + (size_t)m * EMB + n) =
                make_float2(totf(c4[0] * inv0), totf(c4[1] * inv0));
            *(float2*)(C + (size_t)(m + 8) * EMB + n) =
                make_float2(totf(c4[2] * inv1), totf(c4[3] * inv1));
        }
    }
}

// ---- kernel 4: out = att @ Wo + bo. grid (2 ntile, 640 m) -----------------

__global__ __launch_bounds__(256, 2)
void out_mma(const float* __restrict__ bo, float* __restrict__ out) {
    extern __shared__ char smbuf[];
    int t = threadIdx.x;
    int n0 = blockIdx.x * 128, m0 = blockIdx.y * 128;

    float acc[16][4] = {};
    gemm_pipeline(g_att + (size_t)m0 * EMB, 32, EMB,
                  g_wc + (size_t)3 * EMB * EMB + n0, 32 * EMB, EMB,
                  8, acc, smbuf, t);
    store_std(acc, out + (size_t)m0 * EMB + n0, EMB, bo + n0, false, t);
}

// ---- launch ---------------------------------------------------------------

extern "C" void kernel_launch(void* const* d_in, const int* in_sizes, int n_in,
                              void* d_out, int out_size) {
    const float* x  = (const float*)d_in[0];
    const float* Wq = (const float*)d_in[1];
    const float* Wk = (const float*)d_in[2];
    const float* Wv = (const float*)d_in[3];
    const float* Wo = (const float*)d_in[4];
    const float* bo = (const float*)d_in[5];
    float* out = (float*)d_out;

    cudaFuncSetAttribute(qkv_mma, cudaFuncAttributeMaxDynamicSharedMemorySize, SMEM_QKV);
    cudaFuncSetAttribute(qk_mma,  cudaFuncAttributeMaxDynamicSharedMemorySize, SMEMB);
    cudaFuncSetAttribute(av_mma,  cudaFuncAttributeMaxDynamicSharedMemorySize, SMEM_AV);
    cudaFuncSetAttribute(out_mma, cudaFuncAttributeMaxDynamicSharedMemorySize, SMEMB);

    wcvt_kernel<<<256, 256>>>(Wq, Wk, Wv, Wo);
    linit_kernel<<<MROWS / 256, 256>>>();

    qkv_mma<<<dim3(6, MROWS / 128), 256, SMEM_QKV>>>(x);
    qk_mma<<<dim3(3, NB, BATCH), 256, SMEMB>>>();
    av_mma<<<dim3(2, NB, BATCH), 256, SMEM_AV>>>();
    out_mma<<<dim3(2, MROWS / 128), 256, SMEMB>>>(bo, out);
}

// round 11
// speedup vs baseline: 1.8475x; 1.4101x over previous
#include <cuda_runtime.h>
#include <cuda_fp16.h>
#include <cstdint>

#define BATCH 20
#define SEQ   4096
#define EMB   256
#define NB    32
#define BLK   128
#define CTX   384
#define MROWS (BATCH*SEQ)

#define SAH  20                          // fp16 tile stride in b32 words (16 + 4 pad)
#define ABH  (128*SAH*4)                 // 10240 B per stage (128 rows x 32 halves)
#define SMEM_H (6*ABH + 512)             // 61952 B: 3 A + 3 B stages + ls

// Scratch (device globals; no allocations allowed)
__device__ __half g_wh[4*EMB*EMB];                  // transposed fp16 weights [z][n][k]
__device__ __half g_qh[MROWS*EMB];                  // q natural [token][emb]
__device__ __half g_kh[MROWS*EMB];                  // k natural [token][emb]
__device__ __half g_vT[MROWS*EMB];                  // v per 128-block [emb][token]
__device__ __half g_p [(size_t)BATCH*NB*BLK*CTX];   // exp(logits)
__device__ float  g_l [MROWS];                      // softmax row sums
__device__ __half g_ah[MROWS*EMB];                  // attention out (permuted rows)

// ---- primitives -----------------------------------------------------------

__device__ __forceinline__ uint32_t smem_u32(const void* p) {
    uint32_t a;
    asm("{ .reg .u64 t; cvta.to.shared.u64 t, %1; cvt.u32.u64 %0, t; }"
        : "=r"(a) : "l"(p));
    return a;
}

__device__ __forceinline__ uint32_t f2h2(float a, float b) {
    __half2 h = __floats2half2_rn(a, b);
    return *(uint32_t*)&h;
}

__device__ __forceinline__ void cpa16(uint32_t dst, const void* src) {
    asm volatile("cp.async.cg.shared.global [%0], [%1], 16;" :: "r"(dst), "l"(src));
}
#define CP_COMMIT() asm volatile("cp.async.commit_group;" ::: "memory")
#define CP_WAIT1()  asm volatile("cp.async.wait_group 1;" ::: "memory")
#define CP_WAIT0()  asm volatile("cp.async.wait_group 0;" ::: "memory")

__device__ __forceinline__ void mma16h(float c[4], uint32_t a0, uint32_t a1,
                                       uint32_t a2, uint32_t a3,
                                       uint32_t b0, uint32_t b1) {
    asm volatile(
        "mma.sync.aligned.m16n8k16.row.col.f32.f16.f16.f32 "
        "{%0,%1,%2,%3}, {%4,%5,%6,%7}, {%8,%9}, {%0,%1,%2,%3};"
        : "+f"(c[0]), "+f"(c[1]), "+f"(c[2]), "+f"(c[3])
        : "r"(a0), "r"(a1), "r"(a2), "r"(a3), "r"(b0), "r"(b1));
}

// full fp16 tile copy: 128 rows x 32 halves = 8192 B = 512 x 16 B
__device__ __forceinline__ void cpH(uint32_t sD, const __half* __restrict__ src,
                                    int ldh, int t) {
#pragma unroll
    for (int j = 0; j < 2; j++) {
        int idx = j * 256 + t;
        int r = idx >> 2, seg = idx & 3;
        cpa16(sD + (uint32_t)(r * SAH + seg * 4) * 4, src + (size_t)r * ldh + seg * 8);
    }
}

// ---- fp16 warp-tile (64x32) compute, one 32-deep chunk (2 x k16) ----------

__device__ __forceinline__ void mma_chunk_h(const uint32_t* __restrict__ As,
                                            const uint32_t* __restrict__ Bs,
                                            float acc[16][4], int t) {
    int lane = t & 31, w = t >> 5;
    int g = lane >> 2, tig = lane & 3;
    int mbase = (w >> 2) * 64 + g;
    int nbase = (w & 3) * 32 + g;
#pragma unroll
    for (int s = 0; s < 2; s++) {
        int ko = s * 8 + tig;
        uint32_t b[4][2];
#pragma unroll
        for (int nt = 0; nt < 4; nt++) {
            b[nt][0] = Bs[(nbase + nt * 8) * SAH + ko];
            b[nt][1] = Bs[(nbase + nt * 8) * SAH + ko + 4];
        }
#pragma unroll
        for (int mt = 0; mt < 4; mt++) {
            int m = mbase + mt * 16;
            uint32_t a0 = As[m * SAH + ko];
            uint32_t a1 = As[(m + 8) * SAH + ko];
            uint32_t a2 = As[m * SAH + ko + 4];
            uint32_t a3 = As[(m + 8) * SAH + ko + 4];
#pragma unroll
            for (int nt = 0; nt < 4; nt++)
                mma16h(acc[mt * 4 + nt], a0, a1, a2, a3, b[nt][0], b[nt][1]);
        }
    }
}

// ---- fp16 3-stage pipeline, affine A and B chunk sequences ----------------

__device__ __forceinline__ void gemm_pipeline_h(const __half* __restrict__ Abase, int aStep, int lda,
                                                const __half* __restrict__ Bbase, int bStep, int ldb,
                                                int nC, float acc[16][4], char* smem, int t) {
    uint32_t aA[3], bA[3];
    const uint32_t* Ap[3];
    const uint32_t* Bp[3];
#pragma unroll
    for (int i = 0; i < 3; i++) {
        Ap[i] = (const uint32_t*)(smem + i * ABH);
        Bp[i] = (const uint32_t*)(smem + (3 + i) * ABH);
        aA[i] = smem_u32(Ap[i]);
        bA[i] = smem_u32(Bp[i]);
    }
    cpH(aA[0], Abase, lda, t);
    cpH(bA[0], Bbase, ldb, t);
    CP_COMMIT();
    cpH(aA[1], Abase + aStep, lda, t);
    cpH(bA[1], Bbase + bStep, ldb, t);
    CP_COMMIT();

    int bufc = 0, bufn = 2;
    for (int c = 0; c < nC; c++) {
        if (c < nC - 1) CP_WAIT1(); else CP_WAIT0();
        __syncthreads();
        if (c + 2 < nC) {
            cpH(aA[bufn], Abase + (size_t)(c + 2) * aStep, lda, t);
            cpH(bA[bufn], Bbase + (size_t)(c + 2) * bStep, ldb, t);
            CP_COMMIT();
        }
        mma_chunk_h(Ap[bufc], Bp[bufc], acc, t);
        bufc = (bufc == 2) ? 0 : bufc + 1;
        bufn = (bufn == 2) ? 0 : bufn + 1;
    }
}

// ---- epilogues ------------------------------------------------------------

// natural fp16 store [m][n]
__device__ __forceinline__ void store_h(float acc[16][4], __half* __restrict__ C,
                                        int ldc, int t) {
    int lane = t & 31, w = t >> 5;
    int g = lane >> 2, tig = lane & 3;
    int mbase = (w >> 2) * 64 + g;
    int nbase = (w & 3) * 32 + 2 * tig;
#pragma unroll
    for (int mt = 0; mt < 4; mt++) {
#pragma unroll
        for (int nt = 0; nt < 4; nt++) {
            float* c4 = acc[mt * 4 + nt];
            int m = mbase + mt * 16, n = nbase + nt * 8;
            *(__half2*)(C + (size_t)m * ldc + n)       = __floats2half2_rn(c4[0], c4[1]);
            *(__half2*)(C + (size_t)(m + 8) * ldc + n) = __floats2half2_rn(c4[2], c4[3]);
        }
    }
}

// ---- kernel 0: weight cvt + transpose to fp16 [z][n][k] -------------------

__global__ __launch_bounds__(256)
void wcvt_kernel(const float* __restrict__ Wq, const float* __restrict__ Wk,
                 const float* __restrict__ Wv, const float* __restrict__ Wo) {
    int i = blockIdx.x * 256 + threadIdx.x;       // 4*65536 elements
    int z = i >> 16, r = i & 65535;
    int k = r >> 8, n = r & 255;                  // consecutive threads: n fastest (coalesced read)
    const float* src = (z == 0) ? Wq : (z == 1) ? Wk : (z == 2) ? Wv : Wo;
    g_wh[(size_t)z * EMB * EMB + n * EMB + k] = __float2half_rn(src[k * EMB + n]);
}

__global__ __launch_bounds__(256)
void linit_kernel() {
    int i = blockIdx.x * 256 + threadIdx.x;
    int nbi = (i >> 7) & (NB - 1);
    g_l[i] = 128.0f * (float)((nbi == 0) + (nbi == NB - 1));  // exp(0) padded keys
}

// ---- kernel 1: QKV. A from fp32 x via LDG+cvt+STS; grid (6=z*2+nt, 640) ---

__device__ __forceinline__ void ldgA(float4 ar[4], const float* __restrict__ src, int t) {
#pragma unroll
    for (int j = 0; j < 4; j++) {
        int idx = j * 256 + t;
        int m = idx >> 3, k4 = (idx & 7) << 2;
        ar[j] = *(const float4*)(src + (size_t)m * EMB + k4);
    }
}

__device__ __forceinline__ void stsAh(uint32_t* __restrict__ As, const float4 ar[4], int t) {
#pragma unroll
    for (int j = 0; j < 4; j++) {
        int idx = j * 256 + t;
        int m = idx >> 3, k4 = (idx & 7) << 2;
        float4 v = ar[j];
        uint2 u = make_uint2(f2h2(v.x, v.y), f2h2(v.z, v.w));
        *(uint2*)(As + m * SAH + (k4 >> 1)) = u;
    }
}

__global__ __launch_bounds__(256, 2)
void qkv_mma(const float* __restrict__ x) {
    extern __shared__ char smbuf[];
    int t = threadIdx.x;
    int z = blockIdx.x >> 1, ntile = blockIdx.x & 1;
    int m0 = blockIdx.y * 128, n0 = ntile * 128;
    const float* Ax = x + (size_t)m0 * EMB;
    const __half* Bw = g_wh + (size_t)z * EMB * EMB + (size_t)n0 * EMB;

    uint32_t* Ab[2] = {(uint32_t*)smbuf, (uint32_t*)(smbuf + ABH)};
    uint32_t bA[3];
    const uint32_t* Bp[3];
#pragma unroll
    for (int i = 0; i < 3; i++) {
        Bp[i] = (const uint32_t*)(smbuf + (2 + i) * ABH);
        bA[i] = smem_u32(Bp[i]);
    }

    float4 ar[4];
    ldgA(ar, Ax, t);
    cpH(bA[0], Bw, EMB, t);
    CP_COMMIT();
    cpH(bA[1], Bw + 32, EMB, t);
    CP_COMMIT();

    float acc[16][4] = {};
    for (int c = 0; c < 8; c++) {
        stsAh(Ab[c & 1], ar, t);
        if (c < 7) CP_WAIT1(); else CP_WAIT0();
        __syncthreads();
        if (c + 2 < 8) {
            cpH(bA[(c + 2) % 3], Bw + (c + 2) * 32, EMB, t);
            CP_COMMIT();
        }
        if (c + 1 < 8) ldgA(ar, Ax + (c + 1) * 32, t);
        mma_chunk_h(Ab[c & 1], Bp[c % 3], acc, t);
    }

    if (z == 0) {
        store_h(acc, g_qh + (size_t)m0 * EMB + n0, EMB, t);
    } else if (z == 1) {
        store_h(acc, g_kh + (size_t)m0 * EMB + n0, EMB, t);   // natural: col-major B for QK^T
    } else {
        // transposed store [emb][token] within this 128-row block
        __half* VT = g_vT + (size_t)m0 * EMB + (size_t)n0 * 128;
        int lane = t & 31, w = t >> 5;
        int g = lane >> 2, tig = lane & 3;
        int mbase = (w >> 2) * 64 + g;
        int nbase = (w & 3) * 32 + 2 * tig;
#pragma unroll
        for (int mt = 0; mt < 4; mt++) {
#pragma unroll
            for (int nt = 0; nt < 4; nt++) {
                float* c4 = acc[mt * 4 + nt];
                int m = mbase + mt * 16, n = nbase + nt * 8;
                VT[(size_t)n * 128 + m]           = __float2half_rn(c4[0]);
                VT[(size_t)(n + 1) * 128 + m]     = __float2half_rn(c4[1]);
                VT[(size_t)n * 128 + m + 8]       = __float2half_rn(c4[2]);
                VT[(size_t)(n + 1) * 128 + m + 8] = __float2half_rn(c4[3]);
            }
        }
    }
}

// ---- kernel 2: P = exp(Q@K^T/16), row sums. grid (3, NB, B) ---------------

__global__ __launch_bounds__(256, 2)
void qk_mma() {
    extern __shared__ char smbuf[];
    float* ls = (float*)(smbuf + 6 * ABH);
    int t = threadIdx.x;
    int cj = blockIdx.x, nbi = blockIdx.y, b = blockIdx.z;
    int gb = nbi + cj - 1;
    if (gb < 0 || gb >= NB) return;             // padded: handled by linit

    if (t < 128) ls[t] = 0.f;                   // ordered by pipeline's first barrier

    float acc[16][4] = {};
    gemm_pipeline_h(g_qh + (size_t)(b * SEQ + nbi * BLK) * EMB, 32, EMB,
                    g_kh + (size_t)(b * SEQ + gb * BLK) * EMB, 32, EMB,
                    8, acc, smbuf, t);

    __half* P = g_p + ((size_t)(b * NB + nbi) * BLK) * CTX + cj * BLK;
    int lane = t & 31, w = t >> 5;
    int g = lane >> 2, tig = lane & 3;
    int mbase = (w >> 2) * 64 + g;
    int nbase = (w & 3) * 32 + 2 * tig;
    float rsum[8];
#pragma unroll
    for (int i = 0; i < 8; i++) rsum[i] = 0.f;
#pragma unroll
    for (int mt = 0; mt < 4; mt++) {
#pragma unroll
        for (int nt = 0; nt < 4; nt++) {
            float* c4 = acc[mt * 4 + nt];
            int m = mbase + mt * 16, n = nbase + nt * 8;
            float e0 = __expf(c4[0] * 0.0625f);
            float e1 = __expf(c4[1] * 0.0625f);
            float e2 = __expf(c4[2] * 0.0625f);
            float e3 = __expf(c4[3] * 0.0625f);
            rsum[mt * 2 + 0] += e0 + e1;
            rsum[mt * 2 + 1] += e2 + e3;
            *(__half2*)(P + (size_t)m * CTX + n)       = __floats2half2_rn(e0, e1);
            *(__half2*)(P + (size_t)(m + 8) * CTX + n) = __floats2half2_rn(e2, e3);
        }
    }
#pragma unroll
    for (int i = 0; i < 8; i++) {
        rsum[i] += __shfl_xor_sync(0xFFFFFFFFu, rsum[i], 1);
        rsum[i] += __shfl_xor_sync(0xFFFFFFFFu, rsum[i], 2);
    }
    if (tig == 0) {
#pragma unroll
        for (int i = 0; i < 8; i++)
            atomicAdd(&ls[mbase + (i >> 1) * 16 + (i & 1) * 8], rsum[i]);
    }
    __syncthreads();
    if (t < 128)
        atomicAdd(&g_l[(size_t)(b * NB + nbi) * 128 + t], ls[t]);
}

// ---- kernel 3: att = (P @ Vc)/l (fp16), permuted. grid (2, NB, B) ---------

__global__ __launch_bounds__(256, 2)
void av_mma() {
    extern __shared__ char smbuf[];
    int t = threadIdx.x;
    int n0 = blockIdx.x * 128;
    int nbi = blockIdx.y, b = blockIdx.z;

    int lo = (nbi == 0) ? 1 : 0;
    int hi = (nbi == NB - 1) ? 1 : 2;
    int nC = (hi - lo + 1) * 4;                  // 32-token chunks
    int gb0 = nbi + lo - 1;

    const __half* Pb = g_p + (size_t)((b * NB + nbi) * BLK) * CTX + lo * BLK;
    const __half* Vt0 = g_vT + (size_t)(b * SEQ + gb0 * BLK) * EMB + (size_t)n0 * 128;

    uint32_t aA[3], bA[3];
    const uint32_t* Ap[3];
    const uint32_t* Bp[3];
#pragma unroll
    for (int i = 0; i < 3; i++) {
        Ap[i] = (const uint32_t*)(smbuf + i * ABH);
        Bp[i] = (const uint32_t*)(smbuf + (3 + i) * ABH);
        aA[i] = smem_u32(Ap[i]);
        bA[i] = smem_u32(Bp[i]);
    }
#pragma unroll
    for (int i = 0; i < 2; i++) {
        cpH(aA[i], Pb + i * 32, CTX, t);
        cpH(bA[i], Vt0 + ((size_t)(i >> 2) * BLK * EMB) + (i & 3) * 32, 128, t);
        CP_COMMIT();
    }

    float acc[16][4] = {};
    int bufc = 0, bufn = 2;
    for (int c = 0; c < nC; c++) {
        if (c < nC - 1) CP_WAIT1(); else CP_WAIT0();
        __syncthreads();
        if (c + 2 < nC) {
            int cn = c + 2;
            cpH(aA[bufn], Pb + cn * 32, CTX, t);
            cpH(bA[bufn], Vt0 + ((size_t)(cn >> 2) * BLK * EMB) + (cn & 3) * 32, 128, t);
            CP_COMMIT();
        }
        mma_chunk_h(Ap[bufc], Bp[bufc], acc, t);
        bufc = (bufc == 2) ? 0 : bufc + 1;
        bufn = (bufn == 2) ? 0 : bufn + 1;
    }

    const float* lrow = g_l + (size_t)(b * NB + nbi) * 128;
    int rowbase = nbi * (BATCH * BLK) + b * BLK;   // reference transpose (1,0,2,3)
    __half* C = g_ah + (size_t)rowbase * EMB + n0;

    int lane = t & 31, w = t >> 5;
    int g = lane >> 2, tig = lane & 3;
    int mbase = (w >> 2) * 64 + g;
    int nbase = (w & 3) * 32 + 2 * tig;
#pragma unroll
    for (int mt = 0; mt < 4; mt++) {
        int m = mbase + mt * 16;
        float inv0 = 1.0f / lrow[m];
        float inv1 = 1.0f / lrow[m + 8];
#pragma unroll
        for (int nt = 0; nt < 4; nt++) {
            float* c4 = acc[mt * 4 + nt];
            int n = nbase + nt * 8;
            *(__half2*)(C + (size_t)m * EMB + n) =
                __floats2half2_rn(c4[0] * inv0, c4[1] * inv0);
            *(__half2*)(C + (size_t)(m + 8) * EMB + n) =
                __floats2half2_rn(c4[2] * inv1, c4[3] * inv1);
        }
    }
}

// ---- kernel 4: out = att @ Wo + bo (fp32 out). grid (2, 640) --------------

__global__ __launch_bounds__(256, 2)
void out_mma(const float* __restrict__ bo, float* __restrict__ out) {
    extern __shared__ char smbuf[];
    int t = threadIdx.x;
    int n0 = blockIdx.x * 128, m0 = blockIdx.y * 128;

    float acc[16][4] = {};
    gemm_pipeline_h(g_ah + (size_t)m0 * EMB, 32, EMB,
                    g_wh + (size_t)3 * EMB * EMB + (size_t)n0 * EMB, 32, EMB,
                    8, acc, smbuf, t);

    const float* bias = bo + n0;
    float* C = out + (size_t)m0 * EMB + n0;
    int lane = t & 31, w = t >> 5;
    int g = lane >> 2, tig = lane & 3;
    int mbase = (w >> 2) * 64 + g;
    int nbase = (w & 3) * 32 + 2 * tig;
#pragma unroll
    for (int mt = 0; mt < 4; mt++) {
#pragma unroll
        for (int nt = 0; nt < 4; nt++) {
            float* c4 = acc[mt * 4 + nt];
            int m = mbase + mt * 16, n = nbase + nt * 8;
            float b0 = bias[n], b1 = bias[n + 1];
            *(float2*)(C + (size_t)m * EMB + n)       = make_float2(c4[0] + b0, c4[1] + b1);
            *(float2*)(C + (size_t)(m + 8) * EMB + n) = make_float2(c4[2] + b0, c4[3] + b1);
        }
    }
}

// ---- launch ---------------------------------------------------------------

extern "C" void kernel_launch(void* const* d_in, const int* in_sizes, int n_in,
                              void* d_out, int out_size) {
    const float* x  = (const float*)d_in[0];
    const float* Wq = (const float*)d_in[1];
    const float* Wk = (const float*)d_in[2];
    const float* Wv = (const float*)d_in[3];
    const float* Wo = (const float*)d_in[4];
    const float* bo = (const float*)d_in[5];
    float* out = (float*)d_out;

    cudaFuncSetAttribute(qkv_mma, cudaFuncAttributeMaxDynamicSharedMemorySize, SMEM_H);
    cudaFuncSetAttribute(qk_mma,  cudaFuncAttributeMaxDynamicSharedMemorySize, SMEM_H);
    cudaFuncSetAttribute(av_mma,  cudaFuncAttributeMaxDynamicSharedMemorySize, SMEM_H);
    cudaFuncSetAttribute(out_mma, cudaFuncAttributeMaxDynamicSharedMemorySize, SMEM_H);

    wcvt_kernel<<<1024, 256>>>(Wq, Wk, Wv, Wo);
    linit_kernel<<<MROWS / 256, 256>>>();

    qkv_mma<<<dim3(6, MROWS / 128), 256, SMEM_H>>>(x);
    qk_mma<<<dim3(3, NB, BATCH), 256, SMEM_H>>>();
    av_mma<<<dim3(2, NB, BATCH), 256, SMEM_H>>>();
    out_mma<<<dim3(2, MROWS / 128), 256, SMEM_H>>>(bo, out);
}

// round 12
// speedup vs baseline: 1.9199x; 1.0392x over previous
#include <cuda_runtime.h>
#include <cuda_fp16.h>
#include <cstdint>

#define BATCH 20
#define SEQ   4096
#define EMB   256
#define NB    32
#define BLK   128
#define CTX   384
#define MROWS (BATCH*SEQ)

#define SAH  36                          // tile stride in b32 words (32 + 4 pad)
#define ABH  (128*SAH*4)                 // 18432 B per stage (128 rows x 64 halves)
#define SMEM_H (6*ABH + 512)             // 111104 B: 3 A + 3 B stages + ls

// Scratch (device globals; no allocations allowed)
__device__ __half g_xh[MROWS*EMB];                  // x in fp16
__device__ __half g_wh[4*EMB*EMB];                  // transposed fp16 weights [z][n][k]
__device__ __half g_qh[MROWS*EMB];                  // q natural [token][emb]
__device__ __half g_kh[MROWS*EMB];                  // k natural [token][emb]
__device__ __half g_vT[MROWS*EMB];                  // v per 128-block [emb][token]
__device__ __half g_p [(size_t)BATCH*NB*BLK*CTX];   // exp(logits)
__device__ float  g_l [MROWS];                      // softmax row sums
__device__ __half g_ah[MROWS*EMB];                  // attention out (permuted rows)

// ---- primitives -----------------------------------------------------------

__device__ __forceinline__ uint32_t smem_u32(const void* p) {
    uint32_t a;
    asm("{ .reg .u64 t; cvta.to.shared.u64 t, %1; cvt.u32.u64 %0, t; }"
        : "=r"(a) : "l"(p));
    return a;
}

__device__ __forceinline__ uint32_t f2h2(float a, float b) {
    __half2 h = __floats2half2_rn(a, b);
    return *(uint32_t*)&h;
}

__device__ __forceinline__ void cpa16(uint32_t dst, const void* src) {
    asm volatile("cp.async.cg.shared.global [%0], [%1], 16;" :: "r"(dst), "l"(src));
}
#define CP_COMMIT() asm volatile("cp.async.commit_group;" ::: "memory")
#define CP_WAIT1()  asm volatile("cp.async.wait_group 1;" ::: "memory")
#define CP_WAIT0()  asm volatile("cp.async.wait_group 0;" ::: "memory")

__device__ __forceinline__ void mma16h(float c[4], uint32_t a0, uint32_t a1,
                                       uint32_t a2, uint32_t a3,
                                       uint32_t b0, uint32_t b1) {
    asm volatile(
        "mma.sync.aligned.m16n8k16.row.col.f32.f16.f16.f32 "
        "{%0,%1,%2,%3}, {%4,%5,%6,%7}, {%8,%9}, {%0,%1,%2,%3};"
        : "+f"(c[0]), "+f"(c[1]), "+f"(c[2]), "+f"(c[3])
        : "r"(a0), "r"(a1), "r"(a2), "r"(a3), "r"(b0), "r"(b1));
}

// full tile copy: 128 rows x 64 halves = 16384 B = 1024 x 16 B (4 per thread)
__device__ __forceinline__ void cpH(uint32_t sD, const __half* __restrict__ src,
                                    int ldh, int t) {
#pragma unroll
    for (int j = 0; j < 4; j++) {
        int idx = j * 256 + t;
        int r = idx >> 3, seg = idx & 7;
        cpa16(sD + (uint32_t)(r * SAH + seg * 4) * 4, src + (size_t)r * ldh + seg * 8);
    }
}

// ---- fp16 warp-tile (64x32) compute, one 64-deep chunk (4 x k16) ----------

__device__ __forceinline__ void mma_chunk_h(const uint32_t* __restrict__ As,
                                            const uint32_t* __restrict__ Bs,
                                            float acc[16][4], int t) {
    int lane = t & 31, w = t >> 5;
    int g = lane >> 2, tig = lane & 3;
    int mbase = (w >> 2) * 64 + g;
    int nbase = (w & 3) * 32 + g;
#pragma unroll
    for (int s = 0; s < 4; s++) {
        int ko = s * 8 + tig;
        uint32_t b[4][2];
#pragma unroll
        for (int nt = 0; nt < 4; nt++) {
            b[nt][0] = Bs[(nbase + nt * 8) * SAH + ko];
            b[nt][1] = Bs[(nbase + nt * 8) * SAH + ko + 4];
        }
#pragma unroll
        for (int mt = 0; mt < 4; mt++) {
            int m = mbase + mt * 16;
            uint32_t a0 = As[m * SAH + ko];
            uint32_t a1 = As[(m + 8) * SAH + ko];
            uint32_t a2 = As[m * SAH + ko + 4];
            uint32_t a3 = As[(m + 8) * SAH + ko + 4];
#pragma unroll
            for (int nt = 0; nt < 4; nt++)
                mma16h(acc[mt * 4 + nt], a0, a1, a2, a3, b[nt][0], b[nt][1]);
        }
    }
}

// ---- fp16 3-stage pipeline over 64-deep chunks ----------------------------

__device__ __forceinline__ void gemm_pipeline_h(const __half* __restrict__ Abase, int aStep, int lda,
                                                const __half* __restrict__ Bbase, int bStep, int ldb,
                                                int nC, float acc[16][4], char* smem, int t) {
    uint32_t aA[3], bA[3];
    const uint32_t* Ap[3];
    const uint32_t* Bp[3];
#pragma unroll
    for (int i = 0; i < 3; i++) {
        Ap[i] = (const uint32_t*)(smem + i * ABH);
        Bp[i] = (const uint32_t*)(smem + (3 + i) * ABH);
        aA[i] = smem_u32(Ap[i]);
        bA[i] = smem_u32(Bp[i]);
    }
    cpH(aA[0], Abase, lda, t);
    cpH(bA[0], Bbase, ldb, t);
    CP_COMMIT();
    cpH(aA[1], Abase + aStep, lda, t);
    cpH(bA[1], Bbase + bStep, ldb, t);
    CP_COMMIT();

    int bufc = 0, bufn = 2;
    for (int c = 0; c < nC; c++) {
        if (c < nC - 1) CP_WAIT1(); else CP_WAIT0();
        __syncthreads();
        if (c + 2 < nC) {
            cpH(aA[bufn], Abase + (size_t)(c + 2) * aStep, lda, t);
            cpH(bA[bufn], Bbase + (size_t)(c + 2) * bStep, ldb, t);
            CP_COMMIT();
        }
        mma_chunk_h(Ap[bufc], Bp[bufc], acc, t);
        bufc = (bufc == 2) ? 0 : bufc + 1;
        bufn = (bufn == 2) ? 0 : bufn + 1;
    }
}

// ---- epilogues ------------------------------------------------------------

__device__ __forceinline__ void store_h(float acc[16][4], __half* __restrict__ C,
                                        int ldc, int t) {
    int lane = t & 31, w = t >> 5;
    int g = lane >> 2, tig = lane & 3;
    int mbase = (w >> 2) * 64 + g;
    int nbase = (w & 3) * 32 + 2 * tig;
#pragma unroll
    for (int mt = 0; mt < 4; mt++) {
#pragma unroll
        for (int nt = 0; nt < 4; nt++) {
            float* c4 = acc[mt * 4 + nt];
            int m = mbase + mt * 16, n = nbase + nt * 8;
            *(__half2*)(C + (size_t)m * ldc + n)       = __floats2half2_rn(c4[0], c4[1]);
            *(__half2*)(C + (size_t)(m + 8) * ldc + n) = __floats2half2_rn(c4[2], c4[3]);
        }
    }
}

// ---- kernel 0a: x -> fp16 (8 elems/thread) --------------------------------

__global__ __launch_bounds__(256)
void xcvt_kernel(const float* __restrict__ x) {
    int i = blockIdx.x * 256 + threadIdx.x;       // over MROWS*EMB/8
    float4 a = ((const float4*)x)[2 * i];
    float4 b = ((const float4*)x)[2 * i + 1];
    uint4 u = make_uint4(f2h2(a.x, a.y), f2h2(a.z, a.w),
                         f2h2(b.x, b.y), f2h2(b.z, b.w));
    ((uint4*)g_xh)[i] = u;
}

// ---- kernel 0b: weight cvt + transpose to fp16 [z][n][k] ------------------

__global__ __launch_bounds__(256)
void wcvt_kernel(const float* __restrict__ Wq, const float* __restrict__ Wk,
                 const float* __restrict__ Wv, const float* __restrict__ Wo) {
    int i = blockIdx.x * 256 + threadIdx.x;       // 4*65536 elements
    int z = i >> 16, r = i & 65535;
    int k = r >> 8, n = r & 255;
    const float* src = (z == 0) ? Wq : (z == 1) ? Wk : (z == 2) ? Wv : Wo;
    g_wh[(size_t)z * EMB * EMB + n * EMB + k] = __float2half_rn(src[k * EMB + n]);
}

__global__ __launch_bounds__(256)
void linit_kernel() {
    int i = blockIdx.x * 256 + threadIdx.x;
    int nbi = (i >> 7) & (NB - 1);
    g_l[i] = 128.0f * (float)((nbi == 0) + (nbi == NB - 1));  // exp(0) padded keys
}

// ---- kernel 1: QKV (pure fp16 GEMM). grid (6=z*2+nt, 640) -----------------

__global__ __launch_bounds__(256, 2)
void qkv_mma() {
    extern __shared__ char smbuf[];
    int t = threadIdx.x;
    int z = blockIdx.x >> 1, ntile = blockIdx.x & 1;
    int m0 = blockIdx.y * 128, n0 = ntile * 128;

    float acc[16][4] = {};
    gemm_pipeline_h(g_xh + (size_t)m0 * EMB, 64, EMB,
                    g_wh + (size_t)z * EMB * EMB + (size_t)n0 * EMB, 64, EMB,
                    4, acc, smbuf, t);

    if (z == 0) {
        store_h(acc, g_qh + (size_t)m0 * EMB + n0, EMB, t);
    } else if (z == 1) {
        store_h(acc, g_kh + (size_t)m0 * EMB + n0, EMB, t);   // natural: col-major B for QK^T
    } else {
        __half* VT = g_vT + (size_t)m0 * EMB + (size_t)n0 * 128;  // [emb][token]
        int lane = t & 31, w = t >> 5;
        int g = lane >> 2, tig = lane & 3;
        int mbase = (w >> 2) * 64 + g;
        int nbase = (w & 3) * 32 + 2 * tig;
#pragma unroll
        for (int mt = 0; mt < 4; mt++) {
#pragma unroll
            for (int nt = 0; nt < 4; nt++) {
                float* c4 = acc[mt * 4 + nt];
                int m = mbase + mt * 16, n = nbase + nt * 8;
                VT[(size_t)n * 128 + m]           = __float2half_rn(c4[0]);
                VT[(size_t)(n + 1) * 128 + m]     = __float2half_rn(c4[1]);
                VT[(size_t)n * 128 + m + 8]       = __float2half_rn(c4[2]);
                VT[(size_t)(n + 1) * 128 + m + 8] = __float2half_rn(c4[3]);
            }
        }
    }
}

// ---- kernel 2: P = exp(Q@K^T/16), row sums. grid (3, NB, B) ---------------

__global__ __launch_bounds__(256, 2)
void qk_mma() {
    extern __shared__ char smbuf[];
    float* ls = (float*)(smbuf + 6 * ABH);
    int t = threadIdx.x;
    int cj = blockIdx.x, nbi = blockIdx.y, b = blockIdx.z;
    int gb = nbi + cj - 1;
    if (gb < 0 || gb >= NB) return;             // padded: handled by linit

    if (t < 128) ls[t] = 0.f;                   // ordered by pipeline's first barrier

    float acc[16][4] = {};
    gemm_pipeline_h(g_qh + (size_t)(b * SEQ + nbi * BLK) * EMB, 64, EMB,
                    g_kh + (size_t)(b * SEQ + gb * BLK) * EMB, 64, EMB,
                    4, acc, smbuf, t);

    __half* P = g_p + ((size_t)(b * NB + nbi) * BLK) * CTX + cj * BLK;
    int lane = t & 31, w = t >> 5;
    int g = lane >> 2, tig = lane & 3;
    int mbase = (w >> 2) * 64 + g;
    int nbase = (w & 3) * 32 + 2 * tig;
    float rsum[8];
#pragma unroll
    for (int i = 0; i < 8; i++) rsum[i] = 0.f;
#pragma unroll
    for (int mt = 0; mt < 4; mt++) {
#pragma unroll
        for (int nt = 0; nt < 4; nt++) {
            float* c4 = acc[mt * 4 + nt];
            int m = mbase + mt * 16, n = nbase + nt * 8;
            float e0 = __expf(c4[0] * 0.0625f);
            float e1 = __expf(c4[1] * 0.0625f);
            float e2 = __expf(c4[2] * 0.0625f);
            float e3 = __expf(c4[3] * 0.0625f);
            rsum[mt * 2 + 0] += e0 + e1;
            rsum[mt * 2 + 1] += e2 + e3;
            *(__half2*)(P + (size_t)m * CTX + n)       = __floats2half2_rn(e0, e1);
            *(__half2*)(P + (size_t)(m + 8) * CTX + n) = __floats2half2_rn(e2, e3);
        }
    }
#pragma unroll
    for (int i = 0; i < 8; i++) {
        rsum[i] += __shfl_xor_sync(0xFFFFFFFFu, rsum[i], 1);
        rsum[i] += __shfl_xor_sync(0xFFFFFFFFu, rsum[i], 2);
    }
    if (tig == 0) {
#pragma unroll
        for (int i = 0; i < 8; i++)
            atomicAdd(&ls[mbase + (i >> 1) * 16 + (i & 1) * 8], rsum[i]);
    }
    __syncthreads();
    if (t < 128)
        atomicAdd(&g_l[(size_t)(b * NB + nbi) * 128 + t], ls[t]);
}

// ---- kernel 3: att = (P @ Vc)/l (fp16), permuted. grid (2, NB, B) ---------

__global__ __launch_bounds__(256, 2)
void av_mma() {
    extern __shared__ char smbuf[];
    int t = threadIdx.x;
    int n0 = blockIdx.x * 128;
    int nbi = blockIdx.y, b = blockIdx.z;

    int lo = (nbi == 0) ? 1 : 0;
    int hi = (nbi == NB - 1) ? 1 : 2;
    int nC = (hi - lo + 1) * 2;                  // 64-token chunks
    int gb0 = nbi + lo - 1;

    const __half* Pb = g_p + (size_t)((b * NB + nbi) * BLK) * CTX + lo * BLK;
    const __half* Vt0 = g_vT + (size_t)(b * SEQ + gb0 * BLK) * EMB + (size_t)n0 * 128;

    uint32_t aA[3], bA[3];
    const uint32_t* Ap[3];
    const uint32_t* Bp[3];
#pragma unroll
    for (int i = 0; i < 3; i++) {
        Ap[i] = (const uint32_t*)(smbuf + i * ABH);
        Bp[i] = (const uint32_t*)(smbuf + (3 + i) * ABH);
        aA[i] = smem_u32(Ap[i]);
        bA[i] = smem_u32(Bp[i]);
    }
#pragma unroll
    for (int i = 0; i < 2; i++) {
        cpH(aA[i], Pb + i * 64, CTX, t);
        cpH(bA[i], Vt0 + ((size_t)(i >> 1) * BLK * EMB) + (i & 1) * 64, 128, t);
        CP_COMMIT();
    }

    float acc[16][4] = {};
    int bufc = 0, bufn = 2;
    for (int c = 0; c < nC; c++) {
        if (c < nC - 1) CP_WAIT1(); else CP_WAIT0();
        __syncthreads();
        if (c + 2 < nC) {
            int cn = c + 2;
            cpH(aA[bufn], Pb + cn * 64, CTX, t);
            cpH(bA[bufn], Vt0 + ((size_t)(cn >> 1) * BLK * EMB) + (cn & 1) * 64, 128, t);
            CP_COMMIT();
        }
        mma_chunk_h(Ap[bufc], Bp[bufc], acc, t);
        bufc = (bufc == 2) ? 0 : bufc + 1;
        bufn = (bufn == 2) ? 0 : bufn + 1;
    }

    const float* lrow = g_l + (size_t)(b * NB + nbi) * 128;
    int rowbase = nbi * (BATCH * BLK) + b * BLK;   // reference transpose (1,0,2,3)
    __half* C = g_ah + (size_t)rowbase * EMB + n0;

    int lane = t & 31, w = t >> 5;
    int g = lane >> 2, tig = lane & 3;
    int mbase = (w >> 2) * 64 + g;
    int nbase = (w & 3) * 32 + 2 * tig;
#pragma unroll
    for (int mt = 0; mt < 4; mt++) {
        int m = mbase + mt * 16;
        float inv0 = 1.0f / lrow[m];
        float inv1 = 1.0f / lrow[m + 8];
#pragma unroll
        for (int nt = 0; nt < 4; nt++) {
            float* c4 = acc[mt * 4 + nt];
            int n = nbase + nt * 8;
            *(__half2*)(C + (size_t)m * EMB + n) =
                __floats2half2_rn(c4[0] * inv0, c4[1] * inv0);
            *(__half2*)(C + (size_t)(m + 8) * EMB + n) =
                __floats2half2_rn(c4[2] * inv1, c4[3] * inv1);
        }
    }
}

// ---- kernel 4: out = att @ Wo + bo (fp32 out). grid (2, 640) --------------

__global__ __launch_bounds__(256, 2)
void out_mma(const float* __restrict__ bo, float* __restrict__ out) {
    extern __shared__ char smbuf[];
    int t = threadIdx.x;
    int n0 = blockIdx.x * 128, m0 = blockIdx.y * 128;

    float acc[16][4] = {};
    gemm_pipeline_h(g_ah + (size_t)m0 * EMB, 64, EMB,
                    g_wh + (size_t)3 * EMB * EMB + (size_t)n0 * EMB, 64, EMB,
                    4, acc, smbuf, t);

    const float* bias = bo + n0;
    float* C = out + (size_t)m0 * EMB + n0;
    int lane = t & 31, w = t >> 5;
    int g = lane >> 2, tig = lane & 3;
    int mbase = (w >> 2) * 64 + g;
    int nbase = (w & 3) * 32 + 2 * tig;
#pragma unroll
    for (int mt = 0; mt < 4; mt++) {
#pragma unroll
        for (int nt = 0; nt < 4; nt++) {
            float* c4 = acc[mt * 4 + nt];
            int m = mbase + mt * 16, n = nbase + nt * 8;
            float b0 = bias[n], b1 = bias[n + 1];
            *(float2*)(C + (size_t)m * EMB + n)       = make_float2(c4[0] + b0, c4[1] + b1);
            *(float2*)(C + (size_t)(m + 8) * EMB + n) = make_float2(c4[2] + b0, c4[3] + b1);
        }
    }
}

// ---- launch ---------------------------------------------------------------

extern "C" void kernel_launch(void* const* d_in, const int* in_sizes, int n_in,
                              void* d_out, int out_size) {
    const float* x  = (const float*)d_in[0];
    const float* Wq = (const float*)d_in[1];
    const float* Wk = (const float*)d_in[2];
    const float* Wv = (const float*)d_in[3];
    const float* Wo = (const float*)d_in[4];
    const float* bo = (const float*)d_in[5];
    float* out = (float*)d_out;

    cudaFuncSetAttribute(qkv_mma, cudaFuncAttributeMaxDynamicSharedMemorySize, SMEM_H);
    cudaFuncSetAttribute(qk_mma,  cudaFuncAttributeMaxDynamicSharedMemorySize, SMEM_H);
    cudaFuncSetAttribute(av_mma,  cudaFuncAttributeMaxDynamicSharedMemorySize, SMEM_H);
    cudaFuncSetAttribute(out_mma, cudaFuncAttributeMaxDynamicSharedMemorySize, SMEM_H);

    xcvt_kernel<<<MROWS * EMB / 8 / 256, 256>>>(x);
    wcvt_kernel<<<1024, 256>>>(Wq, Wk, Wv, Wo);
    linit_kernel<<<MROWS / 256, 256>>>();

    qkv_mma<<<dim3(6, MROWS / 128), 256, SMEM_H>>>();
    qk_mma<<<dim3(3, NB, BATCH), 256, SMEM_H>>>();
    av_mma<<<dim3(2, NB, BATCH), 256, SMEM_H>>>();
    out_mma<<<dim3(2, MROWS / 128), 256, SMEM_H>>>(bo, out);
}

// round 13
// speedup vs baseline: 2.0923x; 1.0898x over previous
#include <cuda_runtime.h>
#include <cuda_fp16.h>
#include <cstdint>

#define BATCH 20
#define SEQ   4096
#define EMB   256
#define NB    32
#define BLK   128
#define CTX   384
#define MROWS (BATCH*SEQ)

#define SAH  36                          // tile stride in b32 words (32 + 4 pad)
#define ABH  (128*SAH*4)                 // 18432 B per stage (128 rows x 64 halves)
#define SMEM_H (6*ABH + 512)             // 111104 B: 3 A + 3 B stages + ls

// Scratch (device globals; no allocations allowed)
__device__ __half g_xh[MROWS*EMB];                  // x in fp16
__device__ __half g_wh[4*EMB*EMB];                  // transposed fp16 weights [z][n][k]
__device__ __half g_qh[MROWS*EMB];                  // q natural [token][emb]
__device__ __half g_kh[MROWS*EMB];                  // k natural [token][emb]
__device__ __half g_vT[MROWS*EMB];                  // v per 128-block [emb][token]
__device__ __half g_p [(size_t)BATCH*NB*BLK*CTX];   // exp(logits)
__device__ float  g_l [MROWS];                      // softmax row sums
__device__ __half g_ah[MROWS*EMB];                  // attention out (permuted rows)

// ---- primitives -----------------------------------------------------------

__device__ __forceinline__ uint32_t smem_u32(const void* p) {
    uint32_t a;
    asm("{ .reg .u64 t; cvta.to.shared.u64 t, %1; cvt.u32.u64 %0, t; }"
        : "=r"(a) : "l"(p));
    return a;
}

__device__ __forceinline__ uint32_t f2h2(float a, float b) {
    __half2 h = __floats2half2_rn(a, b);
    return *(uint32_t*)&h;
}

__device__ __forceinline__ void cpa16(uint32_t dst, const void* src) {
    asm volatile("cp.async.cg.shared.global [%0], [%1], 16;" :: "r"(dst), "l"(src));
}
#define CP_COMMIT() asm volatile("cp.async.commit_group;" ::: "memory")
#define CP_WAIT1()  asm volatile("cp.async.wait_group 1;" ::: "memory")
#define CP_WAIT0()  asm volatile("cp.async.wait_group 0;" ::: "memory")

__device__ __forceinline__ void mma16h(float c[4], uint32_t a0, uint32_t a1,
                                       uint32_t a2, uint32_t a3,
                                       uint32_t b0, uint32_t b1) {
    asm volatile(
        "mma.sync.aligned.m16n8k16.row.col.f32.f16.f16.f32 "
        "{%0,%1,%2,%3}, {%4,%5,%6,%7}, {%8,%9}, {%0,%1,%2,%3};"
        : "+f"(c[0]), "+f"(c[1]), "+f"(c[2]), "+f"(c[3])
        : "r"(a0), "r"(a1), "r"(a2), "r"(a3), "r"(b0), "r"(b1));
}

__device__ __forceinline__ void ldsm4(uint32_t r[4], uint32_t addr) {
    asm volatile("ldmatrix.sync.aligned.m8n8.x4.shared.b16 {%0,%1,%2,%3}, [%4];"
                 : "=r"(r[0]), "=r"(r[1]), "=r"(r[2]), "=r"(r[3]) : "r"(addr));
}

// full tile copy: 128 rows x 64 halves = 16384 B = 1024 x 16 B (4 per thread)
__device__ __forceinline__ void cpH(uint32_t sD, const __half* __restrict__ src,
                                    int ldh, int t) {
#pragma unroll
    for (int j = 0; j < 4; j++) {
        int idx = j * 256 + t;
        int r = idx >> 3, seg = idx & 7;
        cpa16(sD + (uint32_t)(r * SAH + seg * 4) * 4, src + (size_t)r * ldh + seg * 8);
    }
}

// ---- fp16 warp-tile (64x32), one 64-deep chunk, LDSM fragment loads -------
// Quadrant order of ldmatrix.x4 matches the mma fragment convention:
//   lane L supplies row ((L>>3)&1)*8 + (L&7), k-word offset ((L>>4)&1)*4.

__device__ __forceinline__ void mma_chunk_h(uint32_t sA, uint32_t sB,
                                            float acc[16][4], int t) {
    int lane = t & 31, w = t >> 5;
    int rq = ((lane >> 3) & 1) * 8 + (lane & 7);
    int kq = ((lane >> 4) & 1) * 4;
    uint32_t aAddr = sA + (uint32_t)((((w >> 2) * 64) + rq) * SAH + kq) * 4;
    uint32_t bAddr = sB + (uint32_t)((((w & 3) * 32) + rq) * SAH + kq) * 4;
#pragma unroll
    for (int s = 0; s < 4; s++) {
        uint32_t a[4][4], bp[2][4];
#pragma unroll
        for (int mt = 0; mt < 4; mt++)
            ldsm4(a[mt], aAddr + (uint32_t)(mt * 16 * SAH * 4 + s * 32));
#pragma unroll
        for (int p = 0; p < 2; p++)
            ldsm4(bp[p], bAddr + (uint32_t)(p * 16 * SAH * 4 + s * 32));
#pragma unroll
        for (int mt = 0; mt < 4; mt++)
#pragma unroll
            for (int nt = 0; nt < 4; nt++)
                mma16h(acc[mt * 4 + nt], a[mt][0], a[mt][1], a[mt][2], a[mt][3],
                       bp[nt >> 1][nt & 1], bp[nt >> 1][(nt & 1) + 2]);
    }
}

// ---- fp16 3-stage pipeline over 64-deep chunks ----------------------------

__device__ __forceinline__ void gemm_pipeline_h(const __half* __restrict__ Abase, int aStep, int lda,
                                                const __half* __restrict__ Bbase, int bStep, int ldb,
                                                int nC, float acc[16][4], char* smem, int t) {
    uint32_t aA[3], bA[3];
#pragma unroll
    for (int i = 0; i < 3; i++) {
        aA[i] = smem_u32(smem + i * ABH);
        bA[i] = smem_u32(smem + (3 + i) * ABH);
    }
    cpH(aA[0], Abase, lda, t);
    cpH(bA[0], Bbase, ldb, t);
    CP_COMMIT();
    cpH(aA[1], Abase + aStep, lda, t);
    cpH(bA[1], Bbase + bStep, ldb, t);
    CP_COMMIT();

    int bufc = 0, bufn = 2;
    for (int c = 0; c < nC; c++) {
        if (c < nC - 1) CP_WAIT1(); else CP_WAIT0();
        __syncthreads();
        if (c + 2 < nC) {
            cpH(aA[bufn], Abase + (size_t)(c + 2) * aStep, lda, t);
            cpH(bA[bufn], Bbase + (size_t)(c + 2) * bStep, ldb, t);
            CP_COMMIT();
        }
        mma_chunk_h(aA[bufc], bA[bufc], acc, t);
        bufc = (bufc == 2) ? 0 : bufc + 1;
        bufn = (bufn == 2) ? 0 : bufn + 1;
    }
}

// ---- epilogues ------------------------------------------------------------

__device__ __forceinline__ void store_h(float acc[16][4], __half* __restrict__ C,
                                        int ldc, int t) {
    int lane = t & 31, w = t >> 5;
    int g = lane >> 2, tig = lane & 3;
    int mbase = (w >> 2) * 64 + g;
    int nbase = (w & 3) * 32 + 2 * tig;
#pragma unroll
    for (int mt = 0; mt < 4; mt++) {
#pragma unroll
        for (int nt = 0; nt < 4; nt++) {
            float* c4 = acc[mt * 4 + nt];
            int m = mbase + mt * 16, n = nbase + nt * 8;
            *(__half2*)(C + (size_t)m * ldc + n)       = __floats2half2_rn(c4[0], c4[1]);
            *(__half2*)(C + (size_t)(m + 8) * ldc + n) = __floats2half2_rn(c4[2], c4[3]);
        }
    }
}

// ---- kernel 0a: x -> fp16 (8 elems/thread) --------------------------------

__global__ __launch_bounds__(256)
void xcvt_kernel(const float* __restrict__ x) {
    int i = blockIdx.x * 256 + threadIdx.x;       // over MROWS*EMB/8
    float4 a = ((const float4*)x)[2 * i];
    float4 b = ((const float4*)x)[2 * i + 1];
    uint4 u = make_uint4(f2h2(a.x, a.y), f2h2(a.z, a.w),
                         f2h2(b.x, b.y), f2h2(b.z, b.w));
    ((uint4*)g_xh)[i] = u;
}

// ---- kernel 0b: weight cvt + transpose to fp16 [z][n][k] ------------------

__global__ __launch_bounds__(256)
void wcvt_kernel(const float* __restrict__ Wq, const float* __restrict__ Wk,
                 const float* __restrict__ Wv, const float* __restrict__ Wo) {
    int i = blockIdx.x * 256 + threadIdx.x;       // 4*65536 elements
    int z = i >> 16, r = i & 65535;
    int k = r >> 8, n = r & 255;
    const float* src = (z == 0) ? Wq : (z == 1) ? Wk : (z == 2) ? Wv : Wo;
    g_wh[(size_t)z * EMB * EMB + n * EMB + k] = __float2half_rn(src[k * EMB + n]);
}

__global__ __launch_bounds__(256)
void linit_kernel() {
    int i = blockIdx.x * 256 + threadIdx.x;
    int nbi = (i >> 7) & (NB - 1);
    g_l[i] = 128.0f * (float)((nbi == 0) + (nbi == NB - 1));  // exp(0) padded keys
}

// ---- kernel 1: QKV (pure fp16 GEMM). grid (6=z*2+nt, 640) -----------------

__global__ __launch_bounds__(256, 2)
void qkv_mma() {
    extern __shared__ char smbuf[];
    int t = threadIdx.x;
    int z = blockIdx.x >> 1, ntile = blockIdx.x & 1;
    int m0 = blockIdx.y * 128, n0 = ntile * 128;

    float acc[16][4] = {};
    gemm_pipeline_h(g_xh + (size_t)m0 * EMB, 64, EMB,
                    g_wh + (size_t)z * EMB * EMB + (size_t)n0 * EMB, 64, EMB,
                    4, acc, smbuf, t);

    if (z == 0) {
        store_h(acc, g_qh + (size_t)m0 * EMB + n0, EMB, t);
    } else if (z == 1) {
        store_h(acc, g_kh + (size_t)m0 * EMB + n0, EMB, t);   // natural: col-major B for QK^T
    } else {
        __half* VT = g_vT + (size_t)m0 * EMB + (size_t)n0 * 128;  // [emb][token]
        int lane = t & 31, w = t >> 5;
        int g = lane >> 2, tig = lane & 3;
        int mbase = (w >> 2) * 64 + g;
        int nbase = (w & 3) * 32 + 2 * tig;
#pragma unroll
        for (int mt = 0; mt < 4; mt++) {
#pragma unroll
            for (int nt = 0; nt < 4; nt++) {
                float* c4 = acc[mt * 4 + nt];
                int m = mbase + mt * 16, n = nbase + nt * 8;
                VT[(size_t)n * 128 + m]           = __float2half_rn(c4[0]);
                VT[(size_t)(n + 1) * 128 + m]     = __float2half_rn(c4[1]);
                VT[(size_t)n * 128 + m + 8]       = __float2half_rn(c4[2]);
                VT[(size_t)(n + 1) * 128 + m + 8] = __float2half_rn(c4[3]);
            }
        }
    }
}

// ---- kernel 2: P = exp(Q@K^T/16), row sums. grid (3, NB, B) ---------------

__global__ __launch_bounds__(256, 2)
void qk_mma() {
    extern __shared__ char smbuf[];
    float* ls = (float*)(smbuf + 6 * ABH);
    int t = threadIdx.x;
    int cj = blockIdx.x, nbi = blockIdx.y, b = blockIdx.z;
    int gb = nbi + cj - 1;
    if (gb < 0 || gb >= NB) return;             // padded: handled by linit

    if (t < 128) ls[t] = 0.f;                   // ordered by pipeline's first barrier

    float acc[16][4] = {};
    gemm_pipeline_h(g_qh + (size_t)(b * SEQ + nbi * BLK) * EMB, 64, EMB,
                    g_kh + (size_t)(b * SEQ + gb * BLK) * EMB, 64, EMB,
                    4, acc, smbuf, t);

    __half* P = g_p + ((size_t)(b * NB + nbi) * BLK) * CTX + cj * BLK;
    int lane = t & 31, w = t >> 5;
    int g = lane >> 2, tig = lane & 3;
    int mbase = (w >> 2) * 64 + g;
    int nbase = (w & 3) * 32 + 2 * tig;
    float rsum[8];
#pragma unroll
    for (int i = 0; i < 8; i++) rsum[i] = 0.f;
#pragma unroll
    for (int mt = 0; mt < 4; mt++) {
#pragma unroll
        for (int nt = 0; nt < 4; nt++) {
            float* c4 = acc[mt * 4 + nt];
            int m = mbase + mt * 16, n = nbase + nt * 8;
            float e0 = __expf(c4[0] * 0.0625f);
            float e1 = __expf(c4[1] * 0.0625f);
            float e2 = __expf(c4[2] * 0.0625f);
            float e3 = __expf(c4[3] * 0.0625f);
            rsum[mt * 2 + 0] += e0 + e1;
            rsum[mt * 2 + 1] += e2 + e3;
            *(__half2*)(P + (size_t)m * CTX + n)       = __floats2half2_rn(e0, e1);
            *(__half2*)(P + (size_t)(m + 8) * CTX + n) = __floats2half2_rn(e2, e3);
        }
    }
#pragma unroll
    for (int i = 0; i < 8; i++) {
        rsum[i] += __shfl_xor_sync(0xFFFFFFFFu, rsum[i], 1);
        rsum[i] += __shfl_xor_sync(0xFFFFFFFFu, rsum[i], 2);
    }
    if (tig == 0) {
#pragma unroll
        for (int i = 0; i < 8; i++)
            atomicAdd(&ls[mbase + (i >> 1) * 16 + (i & 1) * 8], rsum[i]);
    }
    __syncthreads();
    if (t < 128)
        atomicAdd(&g_l[(size_t)(b * NB + nbi) * 128 + t], ls[t]);
}

// ---- kernel 3: att = (P @ Vc)/l (fp16), permuted. grid (2, NB, B) ---------

__global__ __launch_bounds__(256, 2)
void av_mma() {
    extern __shared__ char smbuf[];
    int t = threadIdx.x;
    int n0 = blockIdx.x * 128;
    int nbi = blockIdx.y, b = blockIdx.z;

    int lo = (nbi == 0) ? 1 : 0;
    int hi = (nbi == NB - 1) ? 1 : 2;
    int nC = (hi - lo + 1) * 2;                  // 64-token chunks
    int gb0 = nbi + lo - 1;

    const __half* Pb = g_p + (size_t)((b * NB + nbi) * BLK) * CTX + lo * BLK;
    const __half* Vt0 = g_vT + (size_t)(b * SEQ + gb0 * BLK) * EMB + (size_t)n0 * 128;

    uint32_t aA[3], bA[3];
#pragma unroll
    for (int i = 0; i < 3; i++) {
        aA[i] = smem_u32(smbuf + i * ABH);
        bA[i] = smem_u32(smbuf + (3 + i) * ABH);
    }
#pragma unroll
    for (int i = 0; i < 2; i++) {
        cpH(aA[i], Pb + i * 64, CTX, t);
        cpH(bA[i], Vt0 + ((size_t)(i >> 1) * BLK * EMB) + (i & 1) * 64, 128, t);
        CP_COMMIT();
    }

    float acc[16][4] = {};
    int bufc = 0, bufn = 2;
    for (int c = 0; c < nC; c++) {
        if (c < nC - 1) CP_WAIT1(); else CP_WAIT0();
        __syncthreads();
        if (c + 2 < nC) {
            int cn = c + 2;
            cpH(aA[bufn], Pb + cn * 64, CTX, t);
            cpH(bA[bufn], Vt0 + ((size_t)(cn >> 1) * BLK * EMB) + (cn & 1) * 64, 128, t);
            CP_COMMIT();
        }
        mma_chunk_h(aA[bufc], bA[bufc], acc, t);
        bufc = (bufc == 2) ? 0 : bufc + 1;
        bufn = (bufn == 2) ? 0 : bufn + 1;
    }

    const float* lrow = g_l + (size_t)(b * NB + nbi) * 128;
    int rowbase = nbi * (BATCH * BLK) + b * BLK;   // reference transpose (1,0,2,3)
    __half* C = g_ah + (size_t)rowbase * EMB + n0;

    int lane = t & 31, w = t >> 5;
    int g = lane >> 2, tig = lane & 3;
    int mbase = (w >> 2) * 64 + g;
    int nbase = (w & 3) * 32 + 2 * tig;
#pragma unroll
    for (int mt = 0; mt < 4; mt++) {
        int m = mbase + mt * 16;
        float inv0 = 1.0f / lrow[m];
        float inv1 = 1.0f / lrow[m + 8];
#pragma unroll
        for (int nt = 0; nt < 4; nt++) {
            float* c4 = acc[mt * 4 + nt];
            int n = nbase + nt * 8;
            *(__half2*)(C + (size_t)m * EMB + n) =
                __floats2half2_rn(c4[0] * inv0, c4[1] * inv0);
            *(__half2*)(C + (size_t)(m + 8) * EMB + n) =
                __floats2half2_rn(c4[2] * inv1, c4[3] * inv1);
        }
    }
}

// ---- kernel 4: out = att @ Wo + bo (fp32 out). grid (2, 640) --------------

__global__ __launch_bounds__(256, 2)
void out_mma(const float* __restrict__ bo, float* __restrict__ out) {
    extern __shared__ char smbuf[];
    int t = threadIdx.x;
    int n0 = blockIdx.x * 128, m0 = blockIdx.y * 128;

    float acc[16][4] = {};
    gemm_pipeline_h(g_ah + (size_t)m0 * EMB, 64, EMB,
                    g_wh + (size_t)3 * EMB * EMB + (size_t)n0 * EMB, 64, EMB,
                    4, acc, smbuf, t);

    const float* bias = bo + n0;
    float* C = out + (size_t)m0 * EMB + n0;
    int lane = t & 31, w = t >> 5;
    int g = lane >> 2, tig = lane & 3;
    int mbase = (w >> 2) * 64 + g;
    int nbase = (w & 3) * 32 + 2 * tig;
#pragma unroll
    for (int mt = 0; mt < 4; mt++) {
#pragma unroll
        for (int nt = 0; nt < 4; nt++) {
            float* c4 = acc[mt * 4 + nt];
            int m = mbase + mt * 16, n = nbase + nt * 8;
            float b0 = bias[n], b1 = bias[n + 1];
            *(float2*)(C + (size_t)m * EMB + n)       = make_float2(c4[0] + b0, c4[1] + b1);
            *(float2*)(C + (size_t)(m + 8) * EMB + n) = make_float2(c4[2] + b0, c4[3] + b1);
        }
    }
}

// ---- launch ---------------------------------------------------------------

extern "C" void kernel_launch(void* const* d_in, const int* in_sizes, int n_in,
                              void* d_out, int out_size) {
    const float* x  = (const float*)d_in[0];
    const float* Wq = (const float*)d_in[1];
    const float* Wk = (const float*)d_in[2];
    const float* Wv = (const float*)d_in[3];
    const float* Wo = (const float*)d_in[4];
    const float* bo = (const float*)d_in[5];
    float* out = (float*)d_out;

    cudaFuncSetAttribute(qkv_mma, cudaFuncAttributeMaxDynamicSharedMemorySize, SMEM_H);
    cudaFuncSetAttribute(qk_mma,  cudaFuncAttributeMaxDynamicSharedMemorySize, SMEM_H);
    cudaFuncSetAttribute(av_mma,  cudaFuncAttributeMaxDynamicSharedMemorySize, SMEM_H);
    cudaFuncSetAttribute(out_mma, cudaFuncAttributeMaxDynamicSharedMemorySize, SMEM_H);

    xcvt_kernel<<<MROWS * EMB / 8 / 256, 256>>>(x);
    wcvt_kernel<<<1024, 256>>>(Wq, Wk, Wv, Wo);
    linit_kernel<<<MROWS / 256, 256>>>();

    qkv_mma<<<dim3(6, MROWS / 128), 256, SMEM_H>>>();
    qk_mma<<<dim3(3, NB, BATCH), 256, SMEM_H>>>();
    av_mma<<<dim3(2, NB, BATCH), 256, SMEM_H>>>();
    out_mma<<<dim3(2, MROWS / 128), 256, SMEM_H>>>(bo, out);
}

// round 14
// speedup vs baseline: 2.3100x; 1.1041x over previous
#include <cuda_runtime.h>
#include <cuda_fp16.h>
#include <cstdint>

#define BATCH 20
#define SEQ   4096
#define EMB   256
#define NB    32
#define BLK   128
#define CTX   384
#define MROWS (BATCH*SEQ)

// XOR-swizzled tiles, no padding. A stage: 128 rows x 32 words = 16384 B.
// B stage: 64 rows x 32 words = 8192 B. 3 stages each.
#define ABUF_A 16384
#define ABUF_B 8192
#define BOFF   (3*ABUF_A)                // 49152
#define LSOFF  (3*ABUF_A + 3*ABUF_B)     // 73728
#define SMEM_H (LSOFF + 512)             // 74240 B -> 3 CTAs/SM

// Scratch (device globals; no allocations allowed)
__device__ __half g_xh[MROWS*EMB];                  // x in fp16
__device__ __half g_wh[4*EMB*EMB];                  // transposed fp16 weights [z][n][k]
__device__ __half g_qh[MROWS*EMB];                  // q natural [token][emb]
__device__ __half g_kh[MROWS*EMB];                  // k natural [token][emb]
__device__ __half g_vT[MROWS*EMB];                  // v per 128-block [emb][token]
__device__ __half g_p [(size_t)BATCH*NB*BLK*CTX];   // exp(logits)
__device__ float  g_l [MROWS];                      // softmax row sums
__device__ __half g_ah[MROWS*EMB];                  // attention out (permuted rows)

// ---- primitives -----------------------------------------------------------

__device__ __forceinline__ uint32_t smem_u32(const void* p) {
    uint32_t a;
    asm("{ .reg .u64 t; cvta.to.shared.u64 t, %1; cvt.u32.u64 %0, t; }"
        : "=r"(a) : "l"(p));
    return a;
}

__device__ __forceinline__ uint32_t f2h2(float a, float b) {
    __half2 h = __floats2half2_rn(a, b);
    return *(uint32_t*)&h;
}

__device__ __forceinline__ void cpa16(uint32_t dst, const void* src) {
    asm volatile("cp.async.cg.shared.global [%0], [%1], 16;" :: "r"(dst), "l"(src));
}
#define CP_COMMIT() asm volatile("cp.async.commit_group;" ::: "memory")
#define CP_WAIT1()  asm volatile("cp.async.wait_group 1;" ::: "memory")
#define CP_WAIT0()  asm volatile("cp.async.wait_group 0;" ::: "memory")

__device__ __forceinline__ void mma16h(float c[4], uint32_t a0, uint32_t a1,
                                       uint32_t a2, uint32_t a3,
                                       uint32_t b0, uint32_t b1) {
    asm volatile(
        "mma.sync.aligned.m16n8k16.row.col.f32.f16.f16.f32 "
        "{%0,%1,%2,%3}, {%4,%5,%6,%7}, {%8,%9}, {%0,%1,%2,%3};"
        : "+f"(c[0]), "+f"(c[1]), "+f"(c[2]), "+f"(c[3])
        : "r"(a0), "r"(a1), "r"(a2), "r"(a3), "r"(b0), "r"(b1));
}

__device__ __forceinline__ void ldsm4(uint32_t r[4], uint32_t addr) {
    asm volatile("ldmatrix.sync.aligned.m8n8.x4.shared.b16 {%0,%1,%2,%3}, [%4];"
                 : "=r"(r[0]), "=r"(r[1]), "=r"(r[2]), "=r"(r[3]) : "r"(addr));
}

// swizzled word offset within a tile: row r, 4-word group gidx (0..7)
__device__ __forceinline__ uint32_t swz(int r, int gidx) {
    return (uint32_t)(r * 32 + ((gidx ^ (r & 7)) << 2));
}

// A tile copy: 128 rows x 64 halves, swizzled. 4 x 16B per thread.
__device__ __forceinline__ void cpA(uint32_t sD, const __half* __restrict__ src,
                                    int ldh, int t) {
#pragma unroll
    for (int j = 0; j < 4; j++) {
        int idx = j * 256 + t;
        int r = idx >> 3, seg = idx & 7;
        cpa16(sD + swz(r, seg) * 4, src + (size_t)r * ldh + seg * 8);
    }
}

// B tile copy: 64 rows x 64 halves, swizzled. 2 x 16B per thread.
__device__ __forceinline__ void cpB(uint32_t sD, const __half* __restrict__ src,
                                    int ldh, int t) {
#pragma unroll
    for (int j = 0; j < 2; j++) {
        int idx = j * 256 + t;
        int r = idx >> 3, seg = idx & 7;
        cpa16(sD + swz(r, seg) * 4, src + (size_t)r * ldh + seg * 8);
    }
}

// ---- fp16 warp-tile (32x32), one 64-deep chunk, LDSM + swizzle ------------

__device__ __forceinline__ void mma_chunk_h(uint32_t sA, uint32_t sB,
                                            float acc[8][4], int t) {
    int lane = t & 31, w = t >> 5;
    int rq = ((lane >> 3) & 1) * 8 + (lane & 7);
    int kg = (lane >> 4) & 1;                 // which 4-word k-group
    int mrow0 = (w >> 1) * 32 + rq;
    int nrow0 = (w & 1) * 32 + rq;
#pragma unroll
    for (int s = 0; s < 4; s++) {
        uint32_t a[2][4], b[2][4];
#pragma unroll
        for (int mt = 0; mt < 2; mt++) {
            int row = mrow0 + mt * 16;
            ldsm4(a[mt], sA + swz(row, s * 2 + kg) * 4);
        }
#pragma unroll
        for (int p = 0; p < 2; p++) {
            int row = nrow0 + p * 16;
            ldsm4(b[p], sB + swz(row, s * 2 + kg) * 4);
        }
#pragma unroll
        for (int mt = 0; mt < 2; mt++)
#pragma unroll
            for (int nt = 0; nt < 4; nt++)
                mma16h(acc[mt * 4 + nt], a[mt][0], a[mt][1], a[mt][2], a[mt][3],
                       b[nt >> 1][nt & 1], b[nt >> 1][(nt & 1) + 2]);
    }
}

// ---- fp16 3-stage pipeline over 64-deep chunks ----------------------------

__device__ __forceinline__ void gemm_pipeline_h(const __half* __restrict__ Abase, int aStep, int lda,
                                                const __half* __restrict__ Bbase, int bStep, int ldb,
                                                int nC, float acc[8][4], char* smem, int t) {
    uint32_t aA[3], bA[3];
#pragma unroll
    for (int i = 0; i < 3; i++) {
        aA[i] = smem_u32(smem + i * ABUF_A);
        bA[i] = smem_u32(smem + BOFF + i * ABUF_B);
    }
    cpA(aA[0], Abase, lda, t);
    cpB(bA[0], Bbase, ldb, t);
    CP_COMMIT();
    cpA(aA[1], Abase + aStep, lda, t);
    cpB(bA[1], Bbase + bStep, ldb, t);
    CP_COMMIT();

    int bufc = 0, bufn = 2;
    for (int c = 0; c < nC; c++) {
        if (c < nC - 1) CP_WAIT1(); else CP_WAIT0();
        __syncthreads();
        if (c + 2 < nC) {
            cpA(aA[bufn], Abase + (size_t)(c + 2) * aStep, lda, t);
            cpB(bA[bufn], Bbase + (size_t)(c + 2) * bStep, ldb, t);
            CP_COMMIT();
        }
        mma_chunk_h(aA[bufc], bA[bufc], acc, t);
        bufc = (bufc == 2) ? 0 : bufc + 1;
        bufn = (bufn == 2) ? 0 : bufn + 1;
    }
}

// ---- epilogues ------------------------------------------------------------

__device__ __forceinline__ void store_h(float acc[8][4], __half* __restrict__ C,
                                        int ldc, int t) {
    int lane = t & 31, w = t >> 5;
    int g = lane >> 2, tig = lane & 3;
    int mbase = (w >> 1) * 32 + g;
    int nbase = (w & 1) * 32 + 2 * tig;
#pragma unroll
    for (int mt = 0; mt < 2; mt++) {
#pragma unroll
        for (int nt = 0; nt < 4; nt++) {
            float* c4 = acc[mt * 4 + nt];
            int m = mbase + mt * 16, n = nbase + nt * 8;
            *(__half2*)(C + (size_t)m * ldc + n)       = __floats2half2_rn(c4[0], c4[1]);
            *(__half2*)(C + (size_t)(m + 8) * ldc + n) = __floats2half2_rn(c4[2], c4[3]);
        }
    }
}

// ---- helper kernels -------------------------------------------------------

__global__ __launch_bounds__(256)
void xcvt_kernel(const float* __restrict__ x) {
    int i = blockIdx.x * 256 + threadIdx.x;       // over MROWS*EMB/8
    float4 a = ((const float4*)x)[2 * i];
    float4 b = ((const float4*)x)[2 * i + 1];
    uint4 u = make_uint4(f2h2(a.x, a.y), f2h2(a.z, a.w),
                         f2h2(b.x, b.y), f2h2(b.z, b.w));
    ((uint4*)g_xh)[i] = u;
}

__global__ __launch_bounds__(256)
void wcvt_kernel(const float* __restrict__ Wq, const float* __restrict__ Wk,
                 const float* __restrict__ Wv, const float* __restrict__ Wo) {
    int i = blockIdx.x * 256 + threadIdx.x;       // 4*65536 elements
    int z = i >> 16, r = i & 65535;
    int k = r >> 8, n = r & 255;
    const float* src = (z == 0) ? Wq : (z == 1) ? Wk : (z == 2) ? Wv : Wo;
    g_wh[(size_t)z * EMB * EMB + n * EMB + k] = __float2half_rn(src[k * EMB + n]);
}

__global__ __launch_bounds__(256)
void linit_kernel() {
    int i = blockIdx.x * 256 + threadIdx.x;
    int nbi = (i >> 7) & (NB - 1);
    g_l[i] = 128.0f * (float)((nbi == 0) + (nbi == NB - 1));  // exp(0) padded keys
}

// ---- kernel 1: QKV. grid (12 = z*4+nt, 640) -------------------------------

__global__ __launch_bounds__(256, 3)
void qkv_mma() {
    extern __shared__ char smbuf[];
    int t = threadIdx.x;
    int z = blockIdx.x >> 2, ntile = blockIdx.x & 3;
    int m0 = blockIdx.y * 128, n0 = ntile * 64;

    float acc[8][4] = {};
    gemm_pipeline_h(g_xh + (size_t)m0 * EMB, 64, EMB,
                    g_wh + (size_t)z * EMB * EMB + (size_t)n0 * EMB, 64, EMB,
                    4, acc, smbuf, t);

    if (z == 0) {
        store_h(acc, g_qh + (size_t)m0 * EMB + n0, EMB, t);
    } else if (z == 1) {
        store_h(acc, g_kh + (size_t)m0 * EMB + n0, EMB, t);   // natural: col-major B for QK^T
    } else {
        __half* VT = g_vT + (size_t)m0 * EMB + (size_t)n0 * 128;  // [emb][token]
        int lane = t & 31, w = t >> 5;
        int g = lane >> 2, tig = lane & 3;
        int mbase = (w >> 1) * 32 + g;
        int nbase = (w & 1) * 32 + 2 * tig;
#pragma unroll
        for (int mt = 0; mt < 2; mt++) {
#pragma unroll
            for (int nt = 0; nt < 4; nt++) {
                float* c4 = acc[mt * 4 + nt];
                int m = mbase + mt * 16, n = nbase + nt * 8;
                VT[(size_t)n * 128 + m]           = __float2half_rn(c4[0]);
                VT[(size_t)(n + 1) * 128 + m]     = __float2half_rn(c4[1]);
                VT[(size_t)n * 128 + m + 8]       = __float2half_rn(c4[2]);
                VT[(size_t)(n + 1) * 128 + m + 8] = __float2half_rn(c4[3]);
            }
        }
    }
}

// ---- kernel 2: P = exp(Q@K^T/16), row sums. grid (6 = cj*2+nt, NB, B) -----

__global__ __launch_bounds__(256, 3)
void qk_mma() {
    extern __shared__ char smbuf[];
    float* ls = (float*)(smbuf + LSOFF);
    int t = threadIdx.x;
    int cj = blockIdx.x >> 1, ntile = blockIdx.x & 1;
    int nbi = blockIdx.y, b = blockIdx.z;
    int gb = nbi + cj - 1;
    if (gb < 0 || gb >= NB) return;             // padded: handled by linit

    if (t < 128) ls[t] = 0.f;                   // ordered by pipeline's first barrier
    int n0 = ntile * 64;

    float acc[8][4] = {};
    gemm_pipeline_h(g_qh + (size_t)(b * SEQ + nbi * BLK) * EMB, 64, EMB,
                    g_kh + (size_t)(b * SEQ + gb * BLK + n0) * EMB, 64, EMB,
                    4, acc, smbuf, t);

    __half* P = g_p + ((size_t)(b * NB + nbi) * BLK) * CTX + cj * BLK + n0;
    int lane = t & 31, w = t >> 5;
    int g = lane >> 2, tig = lane & 3;
    int mbase = (w >> 1) * 32 + g;
    int nbase = (w & 1) * 32 + 2 * tig;
    float rsum[4] = {0.f, 0.f, 0.f, 0.f};
#pragma unroll
    for (int mt = 0; mt < 2; mt++) {
#pragma unroll
        for (int nt = 0; nt < 4; nt++) {
            float* c4 = acc[mt * 4 + nt];
            int m = mbase + mt * 16, n = nbase + nt * 8;
            float e0 = __expf(c4[0] * 0.0625f);
            float e1 = __expf(c4[1] * 0.0625f);
            float e2 = __expf(c4[2] * 0.0625f);
            float e3 = __expf(c4[3] * 0.0625f);
            rsum[mt * 2 + 0] += e0 + e1;
            rsum[mt * 2 + 1] += e2 + e3;
            *(__half2*)(P + (size_t)m * CTX + n)       = __floats2half2_rn(e0, e1);
            *(__half2*)(P + (size_t)(m + 8) * CTX + n) = __floats2half2_rn(e2, e3);
        }
    }
#pragma unroll
    for (int i = 0; i < 4; i++) {
        rsum[i] += __shfl_xor_sync(0xFFFFFFFFu, rsum[i], 1);
        rsum[i] += __shfl_xor_sync(0xFFFFFFFFu, rsum[i], 2);
    }
    if (tig == 0) {
#pragma unroll
        for (int i = 0; i < 4; i++)
            atomicAdd(&ls[mbase + (i >> 1) * 16 + (i & 1) * 8], rsum[i]);
    }
    __syncthreads();
    if (t < 128)
        atomicAdd(&g_l[(size_t)(b * NB + nbi) * 128 + t], ls[t]);
}

// ---- kernel 3: att = (P @ Vc)/l (fp16), permuted. grid (4, NB, B) ---------

__global__ __launch_bounds__(256, 3)
void av_mma() {
    extern __shared__ char smbuf[];
    int t = threadIdx.x;
    int n0 = blockIdx.x * 64;
    int nbi = blockIdx.y, b = blockIdx.z;

    int lo = (nbi == 0) ? 1 : 0;
    int hi = (nbi == NB - 1) ? 1 : 2;
    int nC = (hi - lo + 1) * 2;                  // 64-token chunks
    int gb0 = nbi + lo - 1;

    const __half* Pb = g_p + (size_t)((b * NB + nbi) * BLK) * CTX + lo * BLK;
    const __half* Vt0 = g_vT + (size_t)(b * SEQ + gb0 * BLK) * EMB + (size_t)n0 * 128;

    uint32_t aA[3], bA[3];
#pragma unroll
    for (int i = 0; i < 3; i++) {
        aA[i] = smem_u32(smbuf + i * ABUF_A);
        bA[i] = smem_u32(smbuf + BOFF + i * ABUF_B);
    }
#pragma unroll
    for (int i = 0; i < 2; i++) {
        cpA(aA[i], Pb + i * 64, CTX, t);
        cpB(bA[i], Vt0 + ((size_t)(i >> 1) * BLK * EMB) + (i & 1) * 64, 128, t);
        CP_COMMIT();
    }

    float acc[8][4] = {};
    int bufc = 0, bufn = 2;
    for (int c = 0; c < nC; c++) {
        if (c < nC - 1) CP_WAIT1(); else CP_WAIT0();
        __syncthreads();
        if (c + 2 < nC) {
            int cn = c + 2;
            cpA(aA[bufn], Pb + cn * 64, CTX, t);
            cpB(bA[bufn], Vt0 + ((size_t)(cn >> 1) * BLK * EMB) + (cn & 1) * 64, 128, t);
            CP_COMMIT();
        }
        mma_chunk_h(aA[bufc], bA[bufc], acc, t);
        bufc = (bufc == 2) ? 0 : bufc + 1;
        bufn = (bufn == 2) ? 0 : bufn + 1;
    }

    const float* lrow = g_l + (size_t)(b * NB + nbi) * 128;
    int rowbase = nbi * (BATCH * BLK) + b * BLK;   // reference transpose (1,0,2,3)
    __half* C = g_ah + (size_t)rowbase * EMB + n0;

    int lane = t & 31, w = t >> 5;
    int g = lane >> 2, tig = lane & 3;
    int mbase = (w >> 1) * 32 + g;
    int nbase = (w & 1) * 32 + 2 * tig;
#pragma unroll
    for (int mt = 0; mt < 2; mt++) {
        int m = mbase + mt * 16;
        float inv0 = 1.0f / lrow[m];
        float inv1 = 1.0f / lrow[m + 8];
#pragma unroll
        for (int nt = 0; nt < 4; nt++) {
            float* c4 = acc[mt * 4 + nt];
            int n = nbase + nt * 8;
            *(__half2*)(C + (size_t)m * EMB + n) =
                __floats2half2_rn(c4[0] * inv0, c4[1] * inv0);
            *(__half2*)(C + (size_t)(m + 8) * EMB + n) =
                __floats2half2_rn(c4[2] * inv1, c4[3] * inv1);
        }
    }
}

// ---- kernel 4: out = att @ Wo + bo (fp32 out). grid (4, 640) --------------

__global__ __launch_bounds__(256, 3)
void out_mma(const float* __restrict__ bo, float* __restrict__ out) {
    extern __shared__ char smbuf[];
    int t = threadIdx.x;
    int n0 = blockIdx.x * 64, m0 = blockIdx.y * 128;

    float acc[8][4] = {};
    gemm_pipeline_h(g_ah + (size_t)m0 * EMB, 64, EMB,
                    g_wh + (size_t)3 * EMB * EMB + (size_t)n0 * EMB, 64, EMB,
                    4, acc, smbuf, t);

    const float* bias = bo + n0;
    float* C = out + (size_t)m0 * EMB + n0;
    int lane = t & 31, w = t >> 5;
    int g = lane >> 2, tig = lane & 3;
    int mbase = (w >> 1) * 32 + g;
    int nbase = (w & 1) * 32 + 2 * tig;
#pragma unroll
    for (int mt = 0; mt < 2; mt++) {
#pragma unroll
        for (int nt = 0; nt < 4; nt++) {
            float* c4 = acc[mt * 4 + nt];
            int m = mbase + mt * 16, n = nbase + nt * 8;
            float b0 = bias[n], b1 = bias[n + 1];
            *(float2*)(C + (size_t)m * EMB + n)       = make_float2(c4[0] + b0, c4[1] + b1);
            *(float2*)(C + (size_t)(m + 8) * EMB + n) = make_float2(c4[2] + b0, c4[3] + b1);
        }
    }
}

// ---- launch ---------------------------------------------------------------

extern "C" void kernel_launch(void* const* d_in, const int* in_sizes, int n_in,
                              void* d_out, int out_size) {
    const float* x  = (const float*)d_in[0];
    const float* Wq = (const float*)d_in[1];
    const float* Wk = (const float*)d_in[2];
    const float* Wv = (const float*)d_in[3];
    const float* Wo = (const float*)d_in[4];
    const float* bo = (const float*)d_in[5];
    float* out = (float*)d_out;

    cudaFuncSetAttribute(qkv_mma, cudaFuncAttributeMaxDynamicSharedMemorySize, SMEM_H);
    cudaFuncSetAttribute(qk_mma,  cudaFuncAttributeMaxDynamicSharedMemorySize, SMEM_H);
    cudaFuncSetAttribute(av_mma,  cudaFuncAttributeMaxDynamicSharedMemorySize, SMEM_H);
    cudaFuncSetAttribute(out_mma, cudaFuncAttributeMaxDynamicSharedMemorySize, SMEM_H);

    xcvt_kernel<<<MROWS * EMB / 8 / 256, 256>>>(x);
    wcvt_kernel<<<1024, 256>>>(Wq, Wk, Wv, Wo);
    linit_kernel<<<MROWS / 256, 256>>>();

    qkv_mma<<<dim3(12, MROWS / 128), 256, SMEM_H>>>();
    qk_mma<<<dim3(6, NB, BATCH), 256, SMEM_H>>>();
    av_mma<<<dim3(4, NB, BATCH), 256, SMEM_H>>>();
    out_mma<<<dim3(4, MROWS / 128), 256, SMEM_H>>>(bo, out);
}

// round 15
// speedup vs baseline: 2.4076x; 1.0423x over previous
#include <cuda_runtime.h>
#include <cuda_fp16.h>
#include <cstdint>

#define BATCH 20
#define SEQ   4096
#define EMB   256
#define NB    32
#define BLK   128
#define CTX   384
#define MROWS (BATCH*SEQ)

// XOR-swizzled tiles (row-stride 32 words = 64 halves), no padding.
#define TILE128 16384                    // 128 rows x 32 words
#define TILE64  8192                     // 64 rows x 32 words
// 32-tile kernels (v, av, out): 3-stage A(128) + 3-stage B(64)
#define BOFF3   (3*TILE128)
#define LSOFF3  (3*TILE128 + 3*TILE64)
#define SMEM_S  (LSOFF3 + 512)           // 74240 B
// 64-tile kernels (qk12, qk): 2-stage A(128) + 2-stage B(128)
#define BOFF2   (2*TILE128)
#define LSOFF2  (4*TILE128)
#define SMEM_Q  (LSOFF2 + 512)           // 66048 B

// Scratch (device globals; no allocations allowed)
__device__ __half g_xh[MROWS*EMB];
__device__ __half g_wh[4*EMB*EMB];                  // transposed fp16 weights [z][n][k]
__device__ __half g_qh[MROWS*EMB];
__device__ __half g_kh[MROWS*EMB];
__device__ __half g_vT[MROWS*EMB];                  // per 128-block [emb][token]
__device__ __half g_p [(size_t)BATCH*NB*BLK*CTX];   // exp(logits)
__device__ float  g_l [MROWS];
__device__ __half g_ah[MROWS*EMB];                  // attention out (permuted rows)

// ---- primitives -----------------------------------------------------------

__device__ __forceinline__ uint32_t smem_u32(const void* p) {
    uint32_t a;
    asm("{ .reg .u64 t; cvta.to.shared.u64 t, %1; cvt.u32.u64 %0, t; }"
        : "=r"(a) : "l"(p));
    return a;
}

__device__ __forceinline__ uint32_t f2h2(float a, float b) {
    __half2 h = __floats2half2_rn(a, b);
    return *(uint32_t*)&h;
}

__device__ __forceinline__ void cpa16(uint32_t dst, const void* src) {
    asm volatile("cp.async.cg.shared.global [%0], [%1], 16;" :: "r"(dst), "l"(src));
}
#define CP_COMMIT() asm volatile("cp.async.commit_group;" ::: "memory")
#define CP_WAIT1()  asm volatile("cp.async.wait_group 1;" ::: "memory")
#define CP_WAIT0()  asm volatile("cp.async.wait_group 0;" ::: "memory")

__device__ __forceinline__ void mma16h(float c[4], uint32_t a0, uint32_t a1,
                                       uint32_t a2, uint32_t a3,
                                       uint32_t b0, uint32_t b1) {
    asm volatile(
        "mma.sync.aligned.m16n8k16.row.col.f32.f16.f16.f32 "
        "{%0,%1,%2,%3}, {%4,%5,%6,%7}, {%8,%9}, {%0,%1,%2,%3};"
        : "+f"(c[0]), "+f"(c[1]), "+f"(c[2]), "+f"(c[3])
        : "r"(a0), "r"(a1), "r"(a2), "r"(a3), "r"(b0), "r"(b1));
}

// fp16-accumulate variant: D/C = 2 x .f16x2 regs
__device__ __forceinline__ void mma16hh(uint32_t c[2], uint32_t a0, uint32_t a1,
                                        uint32_t a2, uint32_t a3,
                                        uint32_t b0, uint32_t b1) {
    asm volatile(
        "mma.sync.aligned.m16n8k16.row.col.f16.f16.f16.f16 "
        "{%0,%1}, {%2,%3,%4,%5}, {%6,%7}, {%0,%1};"
        : "+r"(c[0]), "+r"(c[1])
        : "r"(a0), "r"(a1), "r"(a2), "r"(a3), "r"(b0), "r"(b1));
}

__device__ __forceinline__ void ldsm4(uint32_t r[4], uint32_t addr) {
    asm volatile("ldmatrix.sync.aligned.m8n8.x4.shared.b16 {%0,%1,%2,%3}, [%4];"
                 : "=r"(r[0]), "=r"(r[1]), "=r"(r[2]), "=r"(r[3]) : "r"(addr));
}

// swizzled word offset within a tile: row r, 4-word group gidx (0..7)
__device__ __forceinline__ uint32_t swz(int r, int gidx) {
    return (uint32_t)(r * 32 + ((gidx ^ (r & 7)) << 2));
}

// 128-row tile copy (4 x 16B/thread)
__device__ __forceinline__ void cpT128(uint32_t sD, const __half* __restrict__ src,
                                       int ldh, int t) {
#pragma unroll
    for (int j = 0; j < 4; j++) {
        int idx = j * 256 + t;
        int r = idx >> 3, seg = idx & 7;
        cpa16(sD + swz(r, seg) * 4, src + (size_t)r * ldh + seg * 8);
    }
}

// 64-row tile copy (2 x 16B/thread)
__device__ __forceinline__ void cpT64(uint32_t sD, const __half* __restrict__ src,
                                      int ldh, int t) {
#pragma unroll
    for (int j = 0; j < 2; j++) {
        int idx = j * 256 + t;
        int r = idx >> 3, seg = idx & 7;
        cpa16(sD + swz(r, seg) * 4, src + (size_t)r * ldh + seg * 8);
    }
}

// ---- 32x32 fp32-acc warp tile (v, av, out) --------------------------------

__device__ __forceinline__ void mma_chunk_32(uint32_t sA, uint32_t sB,
                                             float acc[8][4], int t) {
    int lane = t & 31, w = t >> 5;
    int rq = ((lane >> 3) & 1) * 8 + (lane & 7);
    int kg = (lane >> 4) & 1;
    int mrow0 = (w >> 1) * 32 + rq;
    int nrow0 = (w & 1) * 32 + rq;
#pragma unroll
    for (int s = 0; s < 4; s++) {
        uint32_t a[2][4], b[2][4];
#pragma unroll
        for (int mt = 0; mt < 2; mt++)
            ldsm4(a[mt], sA + swz(mrow0 + mt * 16, s * 2 + kg) * 4);
#pragma unroll
        for (int p = 0; p < 2; p++)
            ldsm4(b[p], sB + swz(nrow0 + p * 16, s * 2 + kg) * 4);
#pragma unroll
        for (int mt = 0; mt < 2; mt++)
#pragma unroll
            for (int nt = 0; nt < 4; nt++)
                mma16h(acc[mt * 4 + nt], a[mt][0], a[mt][1], a[mt][2], a[mt][3],
                       b[nt >> 1][nt & 1], b[nt >> 1][(nt & 1) + 2]);
    }
}

__device__ __forceinline__ void gemm3_32(const __half* __restrict__ Abase, int aStep, int lda,
                                         const __half* __restrict__ Bbase, int bStep, int ldb,
                                         int nC, float acc[8][4], char* smem, int t) {
    uint32_t aA[3], bA[3];
#pragma unroll
    for (int i = 0; i < 3; i++) {
        aA[i] = smem_u32(smem + i * TILE128);
        bA[i] = smem_u32(smem + BOFF3 + i * TILE64);
    }
    cpT128(aA[0], Abase, lda, t);
    cpT64(bA[0], Bbase, ldb, t);
    CP_COMMIT();
    cpT128(aA[1], Abase + aStep, lda, t);
    cpT64(bA[1], Bbase + bStep, ldb, t);
    CP_COMMIT();

    int bufc = 0, bufn = 2;
    for (int c = 0; c < nC; c++) {
        if (c < nC - 1) CP_WAIT1(); else CP_WAIT0();
        __syncthreads();
        if (c + 2 < nC) {
            cpT128(aA[bufn], Abase + (size_t)(c + 2) * aStep, lda, t);
            cpT64(bA[bufn], Bbase + (size_t)(c + 2) * bStep, ldb, t);
            CP_COMMIT();
        }
        mma_chunk_32(aA[bufc], bA[bufc], acc, t);
        bufc = (bufc == 2) ? 0 : bufc + 1;
        bufn = (bufn == 2) ? 0 : bufn + 1;
    }
}

// ---- 64x32 fp16-acc warp tile (qk12, qk) ----------------------------------

__device__ __forceinline__ void mma_chunk_64h(uint32_t sA, uint32_t sB,
                                              uint32_t acc[16][2], int t) {
    int lane = t & 31, w = t >> 5;
    int rq = ((lane >> 3) & 1) * 8 + (lane & 7);
    int kg = (lane >> 4) & 1;
    int mrow0 = (w >> 2) * 64 + rq;
    int nrow0 = (w & 3) * 32 + rq;
#pragma unroll
    for (int s = 0; s < 4; s++) {
        uint32_t a[4][4], b[2][4];
#pragma unroll
        for (int mt = 0; mt < 4; mt++)
            ldsm4(a[mt], sA + swz(mrow0 + mt * 16, s * 2 + kg) * 4);
#pragma unroll
        for (int p = 0; p < 2; p++)
            ldsm4(b[p], sB + swz(nrow0 + p * 16, s * 2 + kg) * 4);
#pragma unroll
        for (int mt = 0; mt < 4; mt++)
#pragma unroll
            for (int nt = 0; nt < 4; nt++)
                mma16hh(acc[mt * 4 + nt], a[mt][0], a[mt][1], a[mt][2], a[mt][3],
                        b[nt >> 1][nt & 1], b[nt >> 1][(nt & 1) + 2]);
    }
}

// 2-stage pipeline, both tiles 128 rows
__device__ __forceinline__ void gemm2_64h(const __half* __restrict__ Abase, int aStep, int lda,
                                          const __half* __restrict__ Bbase, int bStep, int ldb,
                                          int nC, uint32_t acc[16][2], char* smem, int t) {
    uint32_t aA[2], bA[2];
#pragma unroll
    for (int i = 0; i < 2; i++) {
        aA[i] = smem_u32(smem + i * TILE128);
        bA[i] = smem_u32(smem + BOFF2 + i * TILE128);
    }
    cpT128(aA[0], Abase, lda, t);
    cpT128(bA[0], Bbase, ldb, t);
    CP_COMMIT();

    for (int c = 0; c < nC; c++) {
        CP_WAIT0();
        __syncthreads();
        if (c + 1 < nC) {
            cpT128(aA[(c + 1) & 1], Abase + (size_t)(c + 1) * aStep, lda, t);
            cpT128(bA[(c + 1) & 1], Bbase + (size_t)(c + 1) * bStep, ldb, t);
            CP_COMMIT();
        }
        mma_chunk_64h(aA[c & 1], bA[c & 1], acc, t);
    }
}

// ---- epilogues ------------------------------------------------------------

__device__ __forceinline__ void store_h32(float acc[8][4], __half* __restrict__ C,
                                          int ldc, int t) {
    int lane = t & 31, w = t >> 5;
    int g = lane >> 2, tig = lane & 3;
    int mbase = (w >> 1) * 32 + g;
    int nbase = (w & 1) * 32 + 2 * tig;
#pragma unroll
    for (int mt = 0; mt < 2; mt++) {
#pragma unroll
        for (int nt = 0; nt < 4; nt++) {
            float* c4 = acc[mt * 4 + nt];
            int m = mbase + mt * 16, n = nbase + nt * 8;
            *(__half2*)(C + (size_t)m * ldc + n)       = __floats2half2_rn(c4[0], c4[1]);
            *(__half2*)(C + (size_t)(m + 8) * ldc + n) = __floats2half2_rn(c4[2], c4[3]);
        }
    }
}

// ---- kernel 0: fused cvt (x + W-transpose + l-init) -----------------------

#define XITEMS (MROWS*EMB/8)
#define WITEMS (4*EMB*EMB)
__global__ __launch_bounds__(256)
void cvt_all(const float* __restrict__ x,
             const float* __restrict__ Wq, const float* __restrict__ Wk,
             const float* __restrict__ Wv, const float* __restrict__ Wo) {
    int i = blockIdx.x * 256 + threadIdx.x;
    if (i < XITEMS) {
        float4 a = ((const float4*)x)[2 * i];
        float4 b = ((const float4*)x)[2 * i + 1];
        ((uint4*)g_xh)[i] = make_uint4(f2h2(a.x, a.y), f2h2(a.z, a.w),
                                       f2h2(b.x, b.y), f2h2(b.z, b.w));
        return;
    }
    int r = i - XITEMS;
    if (r < WITEMS) {
        int z = r >> 16, e = r & 65535;
        int k = e >> 8, n = e & 255;
        const float* src = (z == 0) ? Wq : (z == 1) ? Wk : (z == 2) ? Wv : Wo;
        g_wh[(size_t)z * EMB * EMB + n * EMB + k] = __float2half_rn(src[k * EMB + n]);
        return;
    }
    r -= WITEMS;
    if (r < MROWS) {
        int nbi = (r >> 7) & (NB - 1);
        g_l[r] = 128.0f * (float)((nbi == 0) + (nbi == NB - 1));  // exp(0) padded keys
    }
}

// ---- kernel 1: q,k projections (64x32, fp16 acc). grid (4=z*2+nt, 640) ----

__global__ __launch_bounds__(256, 3)
void qk12_mma() {
    extern __shared__ char smbuf[];
    int t = threadIdx.x;
    int z = blockIdx.x >> 1, ntile = blockIdx.x & 1;
    int m0 = blockIdx.y * 128, n0 = ntile * 128;

    uint32_t acc[16][2] = {};
    gemm2_64h(g_xh + (size_t)m0 * EMB, 64, EMB,
              g_wh + (size_t)z * EMB * EMB + (size_t)n0 * EMB, 64, EMB,
              4, acc, smbuf, t);

    __half* C = (z == 0 ? g_qh : g_kh) + (size_t)m0 * EMB + n0;
    int lane = t & 31, w = t >> 5;
    int g = lane >> 2, tig = lane & 3;
    int mbase = (w >> 2) * 64 + g;
    int nbase = (w & 3) * 32 + 2 * tig;
#pragma unroll
    for (int mt = 0; mt < 4; mt++) {
#pragma unroll
        for (int nt = 0; nt < 4; nt++) {
            int m = mbase + mt * 16, n = nbase + nt * 8;
            *(uint32_t*)(C + (size_t)m * EMB + n)       = acc[mt * 4 + nt][0];
            *(uint32_t*)(C + (size_t)(m + 8) * EMB + n) = acc[mt * 4 + nt][1];
        }
    }
}

// ---- kernel 2: v projection (32x32, fp32 acc). grid (4 nt, 640) -----------

__global__ __launch_bounds__(256, 3)
void v_mma() {
    extern __shared__ char smbuf[];
    int t = threadIdx.x;
    int m0 = blockIdx.y * 128, n0 = blockIdx.x * 64;

    float acc[8][4] = {};
    gemm3_32(g_xh + (size_t)m0 * EMB, 64, EMB,
             g_wh + (size_t)2 * EMB * EMB + (size_t)n0 * EMB, 64, EMB,
             4, acc, smbuf, t);

    __half* VT = g_vT + (size_t)m0 * EMB + (size_t)n0 * 128;  // [emb][token]
    int lane = t & 31, w = t >> 5;
    int g = lane >> 2, tig = lane & 3;
    int mbase = (w >> 1) * 32 + g;
    int nbase = (w & 1) * 32 + 2 * tig;
#pragma unroll
    for (int mt = 0; mt < 2; mt++) {
#pragma unroll
        for (int nt = 0; nt < 4; nt++) {
            float* c4 = acc[mt * 4 + nt];
            int m = mbase + mt * 16, n = nbase + nt * 8;
            VT[(size_t)n * 128 + m]           = __float2half_rn(c4[0]);
            VT[(size_t)(n + 1) * 128 + m]     = __float2half_rn(c4[1]);
            VT[(size_t)n * 128 + m + 8]       = __float2half_rn(c4[2]);
            VT[(size_t)(n + 1) * 128 + m + 8] = __float2half_rn(c4[3]);
        }
    }
}

// ---- kernel 3: P = exp(Q@K^T/16) (64x32 fp16 acc), sums. grid (3,NB,B) ----

__global__ __launch_bounds__(256, 3)
void qk_mma() {
    extern __shared__ char smbuf[];
    float* ls = (float*)(smbuf + LSOFF2);
    int t = threadIdx.x;
    int cj = blockIdx.x, nbi = blockIdx.y, b = blockIdx.z;
    int gb = nbi + cj - 1;
    if (gb < 0 || gb >= NB) return;             // padded: handled in cvt_all

    if (t < 128) ls[t] = 0.f;                   // ordered by pipeline's first barrier

    uint32_t acc[16][2] = {};
    gemm2_64h(g_qh + (size_t)(b * SEQ + nbi * BLK) * EMB, 64, EMB,
              g_kh + (size_t)(b * SEQ + gb * BLK) * EMB, 64, EMB,
              4, acc, smbuf, t);

    __half* P = g_p + ((size_t)(b * NB + nbi) * BLK) * CTX + cj * BLK;
    int lane = t & 31, w = t >> 5;
    int g = lane >> 2, tig = lane & 3;
    int mbase = (w >> 2) * 64 + g;
    int nbase = (w & 3) * 32 + 2 * tig;
    float rsum[8];
#pragma unroll
    for (int i = 0; i < 8; i++) rsum[i] = 0.f;
#pragma unroll
    for (int mt = 0; mt < 4; mt++) {
#pragma unroll
        for (int nt = 0; nt < 4; nt++) {
            int m = mbase + mt * 16, n = nbase + nt * 8;
            float2 v0 = __half22float2(*(__half2*)&acc[mt * 4 + nt][0]);
            float2 v1 = __half22float2(*(__half2*)&acc[mt * 4 + nt][1]);
            float e0 = __expf(v0.x * 0.0625f);
            float e1 = __expf(v0.y * 0.0625f);
            float e2 = __expf(v1.x * 0.0625f);
            float e3 = __expf(v1.y * 0.0625f);
            rsum[mt * 2 + 0] += e0 + e1;
            rsum[mt * 2 + 1] += e2 + e3;
            *(__half2*)(P + (size_t)m * CTX + n)       = __floats2half2_rn(e0, e1);
            *(__half2*)(P + (size_t)(m + 8) * CTX + n) = __floats2half2_rn(e2, e3);
        }
    }
#pragma unroll
    for (int i = 0; i < 8; i++) {
        rsum[i] += __shfl_xor_sync(0xFFFFFFFFu, rsum[i], 1);
        rsum[i] += __shfl_xor_sync(0xFFFFFFFFu, rsum[i], 2);
    }
    if (tig == 0) {
#pragma unroll
        for (int i = 0; i < 8; i++)
            atomicAdd(&ls[mbase + (i >> 1) * 16 + (i & 1) * 8], rsum[i]);
    }
    __syncthreads();
    if (t < 128)
        atomicAdd(&g_l[(size_t)(b * NB + nbi) * 128 + t], ls[t]);
}

// ---- kernel 4: att = (P @ Vc)/l (fp16), permuted. grid (4, NB, B) ---------

__global__ __launch_bounds__(256, 3)
void av_mma() {
    extern __shared__ char smbuf[];
    int t = threadIdx.x;
    int n0 = blockIdx.x * 64;
    int nbi = blockIdx.y, b = blockIdx.z;

    int lo = (nbi == 0) ? 1 : 0;
    int hi = (nbi == NB - 1) ? 1 : 2;
    int nC = (hi - lo + 1) * 2;                  // 64-token chunks
    int gb0 = nbi + lo - 1;

    const __half* Pb = g_p + (size_t)((b * NB + nbi) * BLK) * CTX + lo * BLK;
    const __half* Vt0 = g_vT + (size_t)(b * SEQ + gb0 * BLK) * EMB + (size_t)n0 * 128;

    uint32_t aA[3], bA[3];
#pragma unroll
    for (int i = 0; i < 3; i++) {
        aA[i] = smem_u32(smbuf + i * TILE128);
        bA[i] = smem_u32(smbuf + BOFF3 + i * TILE64);
    }
#pragma unroll
    for (int i = 0; i < 2; i++) {
        cpT128(aA[i], Pb + i * 64, CTX, t);
        cpT64(bA[i], Vt0 + ((size_t)(i >> 1) * BLK * EMB) + (i & 1) * 64, 128, t);
        CP_COMMIT();
    }

    float acc[8][4] = {};
    int bufc = 0, bufn = 2;
    for (int c = 0; c < nC; c++) {
        if (c < nC - 1) CP_WAIT1(); else CP_WAIT0();
        __syncthreads();
        if (c + 2 < nC) {
            int cn = c + 2;
            cpT128(aA[bufn], Pb + cn * 64, CTX, t);
            cpT64(bA[bufn], Vt0 + ((size_t)(cn >> 1) * BLK * EMB) + (cn & 1) * 64, 128, t);
            CP_COMMIT();
        }
        mma_chunk_32(aA[bufc], bA[bufc], acc, t);
        bufc = (bufc == 2) ? 0 : bufc + 1;
        bufn = (bufn == 2) ? 0 : bufn + 1;
    }

    const float* lrow = g_l + (size_t)(b * NB + nbi) * 128;
    int rowbase = nbi * (BATCH * BLK) + b * BLK;   // reference transpose (1,0,2,3)
    __half* C = g_ah + (size_t)rowbase * EMB + n0;

    int lane = t & 31, w = t >> 5;
    int g = lane >> 2, tig = lane & 3;
    int mbase = (w >> 1) * 32 + g;
    int nbase = (w & 1) * 32 + 2 * tig;
#pragma unroll
    for (int mt = 0; mt < 2; mt++) {
        int m = mbase + mt * 16;
        float inv0 = 1.0f / lrow[m];
        float inv1 = 1.0f / lrow[m + 8];
#pragma unroll
        for (int nt = 0; nt < 4; nt++) {
            float* c4 = acc[mt * 4 + nt];
            int n = nbase + nt * 8;
            *(__half2*)(C + (size_t)m * EMB + n) =
                __floats2half2_rn(c4[0] * inv0, c4[1] * inv0);
            *(__half2*)(C + (size_t)(m + 8) * EMB + n) =
                __floats2half2_rn(c4[2] * inv1, c4[3] * inv1);
        }
    }
}

// ---- kernel 5: out = att @ Wo + bo (fp32 out). grid (4, 640) --------------

__global__ __launch_bounds__(256, 3)
void out_mma(const float* __restrict__ bo, float* __restrict__ out) {
    extern __shared__ char smbuf[];
    int t = threadIdx.x;
    int n0 = blockIdx.x * 64, m0 = blockIdx.y * 128;

    float acc[8][4] = {};
    gemm3_32(g_ah + (size_t)m0 * EMB, 64, EMB,
             g_wh + (size_t)3 * EMB * EMB + (size_t)n0 * EMB, 64, EMB,
             4, acc, smbuf, t);

    const float* bias = bo + n0;
    float* C = out + (size_t)m0 * EMB + n0;
    int lane = t & 31, w = t >> 5;
    int g = lane >> 2, tig = lane & 3;
    int mbase = (w >> 1) * 32 + g;
    int nbase = (w & 1) * 32 + 2 * tig;
#pragma unroll
    for (int mt = 0; mt < 2; mt++) {
#pragma unroll
        for (int nt = 0; nt < 4; nt++) {
            float* c4 = acc[mt * 4 + nt];
            int m = mbase + mt * 16, n = nbase + nt * 8;
            float b0 = bias[n], b1 = bias[n + 1];
            *(float2*)(C + (size_t)m * EMB + n)       = make_float2(c4[0] + b0, c4[1] + b1);
            *(float2*)(C + (size_t)(m + 8) * EMB + n) = make_float2(c4[2] + b0, c4[3] + b1);
        }
    }
}

// ---- launch ---------------------------------------------------------------

extern "C" void kernel_launch(void* const* d_in, const int* in_sizes, int n_in,
                              void* d_out, int out_size) {
    const float* x  = (const float*)d_in[0];
    const float* Wq = (const float*)d_in[1];
    const float* Wk = (const float*)d_in[2];
    const float* Wv = (const float*)d_in[3];
    const float* Wo = (const float*)d_in[4];
    const float* bo = (const float*)d_in[5];
    float* out = (float*)d_out;

    cudaFuncSetAttribute(qk12_mma, cudaFuncAttributeMaxDynamicSharedMemorySize, SMEM_Q);
    cudaFuncSetAttribute(qk_mma,   cudaFuncAttributeMaxDynamicSharedMemorySize, SMEM_Q);
    cudaFuncSetAttribute(v_mma,    cudaFuncAttributeMaxDynamicSharedMemorySize, SMEM_S);
    cudaFuncSetAttribute(av_mma,   cudaFuncAttributeMaxDynamicSharedMemorySize, SMEM_S);
    cudaFuncSetAttribute(out_mma,  cudaFuncAttributeMaxDynamicSharedMemorySize, SMEM_S);

    int total = XITEMS + WITEMS + MROWS;
    cvt_all<<<(total + 255) / 256, 256>>>(x, Wq, Wk, Wv, Wo);

    qk12_mma<<<dim3(4, MROWS / 128), 256, SMEM_Q>>>();
    v_mma<<<dim3(4, MROWS / 128), 256, SMEM_S>>>();
    qk_mma<<<dim3(3, NB, BATCH), 256, SMEM_Q>>>();
    av_mma<<<dim3(4, NB, BATCH), 256, SMEM_S>>>();
    out_mma<<<dim3(4, MROWS / 128), 256, SMEM_S>>>(bo, out);
}